// round 12
// baseline (speedup 1.0000x reference)
#include <cuda_runtime.h>
#include <cuda_bf16.h>
#include <math.h>
#include <stdint.h>

#define NN 50000
#define NE 800000
#define NBLK ((NN + 1023) / 1024)
#define MB_ALL 391

// ---------------- scratch (static device globals; no allocation) -------------
__device__ int   g_cnt[NN];
__device__ int   g_rowptr[NN + 1];
__device__ int   g_cursor[NN];
__device__ int   g_colsrc[NE];
__device__ int   g_bsum[64];
__device__ float g_dinv[NN];

__device__ float g_h128[(size_t)NN * 128];
__device__ float g_h256[(size_t)NN * 256];
__device__ float g_t64 [(size_t)NN * 64];

__device__ __align__(256) __nv_bfloat16 g_h64h [(size_t)NN * 64],  g_h64l [(size_t)NN * 64];
__device__ __align__(256) __nv_bfloat16 g_p128h[(size_t)NN * 128], g_p128l[(size_t)NN * 128];
__device__ __align__(256) __nv_bfloat16 g_p256h[(size_t)NN * 256], g_p256l[(size_t)NN * 256];
__device__ __align__(256) __nv_bfloat16 g_h512h[(size_t)NN * 512], g_h512l[(size_t)NN * 512];

__device__ __align__(256) __nv_bfloat16 g_w3h[128 * 64],  g_w3l[128 * 64];
__device__ __align__(256) __nv_bfloat16 g_g1h[256 * 128], g_g1l[256 * 128];
__device__ __align__(256) __nv_bfloat16 g_g2h[512 * 256], g_g2l[512 * 256];
__device__ __align__(256) __nv_bfloat16 g_g3h[50 * 512],  g_g3l[50 * 512];

// ---------------- helpers ------------------------------------------------------
__device__ __forceinline__ void split1(float x, float& hi, float& lo) {
    __nv_bfloat16 h = __float2bfloat16(x);
    hi = __bfloat162float(h);
    lo = x - hi;
}
__device__ __forceinline__ void mma16(float c[4], const uint32_t a[4], uint32_t b0, uint32_t b1) {
    asm("mma.sync.aligned.m16n8k16.row.col.f32.bf16.bf16.f32 "
        "{%0,%1,%2,%3},{%4,%5,%6,%7},{%8,%9},{%0,%1,%2,%3};"
        : "+f"(c[0]), "+f"(c[1]), "+f"(c[2]), "+f"(c[3])
        : "r"(a[0]), "r"(a[1]), "r"(a[2]), "r"(a[3]), "r"(b0), "r"(b1));
}
__device__ __forceinline__ void ldm_x4(uint32_t r[4], uint32_t saddr) {
    asm volatile("ldmatrix.sync.aligned.m8n8.x4.shared.b16 {%0,%1,%2,%3}, [%4];"
        : "=r"(r[0]), "=r"(r[1]), "=r"(r[2]), "=r"(r[3]) : "r"(saddr));
}
__device__ __forceinline__ uint32_t smem_u32(const void* p) {
    uint32_t a;
    asm("{ .reg .u64 t; cvta.to.shared.u64 t, %1; cvt.u32.u64 %0, t; }" : "=r"(a) : "l"(p));
    return a;
}
__device__ __forceinline__ void cpa16(uint32_t dst, const void* src, bool pred) {
    int sz = pred ? 16 : 0;
    asm volatile("cp.async.cg.shared.global [%0], [%1], 16, %2;"
        :: "r"(dst), "l"(src), "r"(sz));
}
#define CP_COMMIT() asm volatile("cp.async.commit_group;")
#define CP_WAIT0()  asm volatile("cp.async.wait_group 0;")

// ---------------- degree / CSR build -----------------------------------------
__global__ void k_zero_cnt() {
    int i = blockIdx.x * blockDim.x + threadIdx.x;
    if (i < NN) g_cnt[i] = 0;
}
__global__ void k_count(const int* __restrict__ ei) {
    int e = blockIdx.x * blockDim.x + threadIdx.x;
    if (e < NE) {
        int dst = ei[NE + e];
        if ((unsigned)dst < NN) atomicAdd(&g_cnt[dst], 1);
    }
}
__global__ void k_scan1() {
    __shared__ int sh[1024];
    int tid = threadIdx.x;
    int i = blockIdx.x * 1024 + tid;
    int v = (i < NN) ? g_cnt[i] : 0;
    if (i < NN) g_dinv[i] = rsqrtf((float)v + 1.0f);
    sh[tid] = v;
    __syncthreads();
    for (int off = 1; off < 1024; off <<= 1) {
        int t = (tid >= off) ? sh[tid - off] : 0;
        __syncthreads();
        sh[tid] += t;
        __syncthreads();
    }
    if (i < NN) g_rowptr[i] = sh[tid] - v;
    if (tid == 1023) g_bsum[blockIdx.x] = sh[1023];
}
__global__ void k_scan2() {
    __shared__ int sh[64];
    int tid = threadIdx.x;
    int v = (tid < NBLK) ? g_bsum[tid] : 0;
    sh[tid] = v;
    __syncthreads();
    for (int off = 1; off < 64; off <<= 1) {
        int t = (tid >= off) ? sh[tid - off] : 0;
        __syncthreads();
        sh[tid] += t;
        __syncthreads();
    }
    g_bsum[tid] = sh[tid] - v;
}
__global__ void k_scan3() {
    int i = blockIdx.x * blockDim.x + threadIdx.x;
    if (i < NN) {
        int r = g_rowptr[i] + g_bsum[i >> 10];
        g_rowptr[i] = r;
        g_cursor[i] = r;
    }
    if (i == 0) g_rowptr[NN] = NE;
}
__global__ void k_scatter(const int* __restrict__ ei) {
    int e = blockIdx.x * blockDim.x + threadIdx.x;
    if (e < NE) {
        int dst = ei[NE + e];
        int src = ei[e];
        if ((unsigned)dst < NN && (unsigned)src < NN) {
            int pos = atomicAdd(&g_cursor[dst], 1);
            if ((unsigned)pos < NE) g_colsrc[pos] = src;
        }
    }
}

// ---------------- weight split + transpose -------------------------------------
__global__ void k_split_t(const float* __restrict__ src, __nv_bfloat16* __restrict__ hi,
                          __nv_bfloat16* __restrict__ lo, int K, int N) {
    int i = blockIdx.x * blockDim.x + threadIdx.x;
    if (i < K * N) {
        int k = i / N, n = i % N;
        float x = src[i];
        float h, l;
        split1(x, h, l);
        hi[(size_t)n * K + k] = __float2bfloat16(h);
        lo[(size_t)n * K + k] = __float2bfloat16(l);
    }
}

// ---------------- fused MLP1+MLP2 (3 -> 32 -> 64), writes h64 planes ----------
__global__ __launch_bounds__(256)
void k_mlp12(const float* __restrict__ x,
             const float* __restrict__ w1, const float* __restrict__ b1,
             const float* __restrict__ w2, const float* __restrict__ b2,
             __nv_bfloat16* __restrict__ hh, __nv_bfloat16* __restrict__ hl) {
    __shared__ float sw1[96], sb1[32], sw2[32 * 64], sb2[64];
    int tid = threadIdx.x;
    if (tid < 96) sw1[tid] = w1[tid];
    if (tid < 32) sb1[tid] = b1[tid];
    if (tid < 64) sb2[tid] = b2[tid];
    for (int i = tid; i < 32 * 64; i += 256) sw2[i] = w2[i];
    __syncthreads();

    int v = blockIdx.x * 256 + tid;
    if (v >= NN) return;
    float x0 = x[3 * v], x1 = x[3 * v + 1], x2 = x[3 * v + 2];

    float h32[32];
#pragma unroll
    for (int j = 0; j < 32; j++)
        h32[j] = fmaxf(x0 * sw1[j] + x1 * sw1[32 + j] + x2 * sw1[64 + j] + sb1[j], 0.f);

    __nv_bfloat162* ph = (__nv_bfloat162*)(hh + (size_t)v * 64);
    __nv_bfloat162* pl = (__nv_bfloat162*)(hl + (size_t)v * 64);
#pragma unroll 4
    for (int j = 0; j < 64; j += 2) {
        float a0 = sb2[j], a1 = sb2[j + 1];
#pragma unroll
        for (int k = 0; k < 32; k++) {
            float hk = h32[k];
            a0 += hk * sw2[k * 64 + j];
            a1 += hk * sw2[k * 64 + j + 1];
        }
        a0 = fmaxf(a0, 0.f);
        a1 = fmaxf(a1, 0.f);
        float h0, l0, h1, l1;
        split1(a0, h0, l0);
        split1(a1, h1, l1);
        ph[j >> 1] = __floats2bfloat162_rn(h0, h1);
        pl[j >> 1] = __floats2bfloat162_rn(l0, l1);
    }
}

// ---------------- bf16x3 tensor-core GEMM (cp.async staging) -------------------
template <int BN, bool RELU, bool BIAS, bool OUTP>
__global__ __launch_bounds__(256)
void k_gemm_bf(const __nv_bfloat16* __restrict__ Ahi, const __nv_bfloat16* __restrict__ Alo,
               const __nv_bfloat16* __restrict__ Whi, const __nv_bfloat16* __restrict__ Wlo,
               const float* __restrict__ bias,
               float* __restrict__ Cf,
               __nv_bfloat16* __restrict__ Chi, __nv_bfloat16* __restrict__ Clo,
               int M, int K, int Ntrue, int Npad) {
    constexpr int BM = 128, BK = 32, ASTR = 40;
    constexpr int A_H = BM * ASTR;
    constexpr int B_H = BN * ASTR;
    constexpr int STAGE = 2 * A_H + 2 * B_H;
    constexpr int OAH = 0, OAL = A_H, OBH = 2 * A_H, OBL = 2 * A_H + B_H;
    constexpr int NJ = (BN / 2) / 8;
    constexpr int TPN = 256 / BN;
    constexpr int KSEG = BK / TPN;
    constexpr int NV = KSEG / 8;

    extern __shared__ __nv_bfloat16 sm[];
    const uint32_t smb = smem_u32(sm);
    int tid = threadIdx.x, lane = tid & 31, wid = tid >> 5;
    int wm = (wid & 3) * 32, wn = (wid >> 2) * (BN / 2);
    int bm0 = blockIdx.x * BM, bn0 = blockIdx.y * BN;

    float c[2][NJ][4];
#pragma unroll
    for (int mi = 0; mi < 2; mi++)
#pragma unroll
        for (int nj = 0; nj < NJ; nj++)
#pragma unroll
            for (int r = 0; r < 4; r++) c[mi][nj][r] = 0.f;

    int arow = tid >> 1, ahalf = tid & 1;
    int brow = tid / TPN, bseg = tid % TPN;
    bool aok = (bm0 + arow) < M;
    bool bok = (bn0 + brow) < Ntrue;
    const __nv_bfloat16* pAh = Ahi + (size_t)(bm0 + arow) * K + ahalf * 16;
    const __nv_bfloat16* pAl = Alo + (size_t)(bm0 + arow) * K + ahalf * 16;
    const __nv_bfloat16* pBh = Whi + (size_t)(bn0 + brow) * K + bseg * KSEG;
    const __nv_bfloat16* pBl = Wlo + (size_t)(bn0 + brow) * K + bseg * KSEG;
    uint32_t dA = smb + ((uint32_t)arow * ASTR + ahalf * 16) * 2;
    uint32_t dB = smb + ((uint32_t)brow * ASTR + bseg * KSEG) * 2;

    auto stage_in = [&](int kt) {
        int k0 = kt * BK;
        uint32_t so = (uint32_t)((kt & 1) * STAGE) * 2;
        cpa16(so + dA + OAH * 2,      pAh + k0,     aok);
        cpa16(so + dA + OAH * 2 + 16, pAh + k0 + 8, aok);
        cpa16(so + dA + OAL * 2,      pAl + k0,     aok);
        cpa16(so + dA + OAL * 2 + 16, pAl + k0 + 8, aok);
#pragma unroll
        for (int v = 0; v < NV; v++) {
            cpa16(so + dB + OBH * 2 + v * 16, pBh + k0 + v * 8, bok);
            cpa16(so + dB + OBL * 2 + v * 16, pBl + k0 + v * 8, bok);
        }
        CP_COMMIT();
    };

    auto comp = [&](int buf) {
        uint32_t st = smb + (uint32_t)(buf * STAGE) * 2;
#pragma unroll
        for (int ch = 0; ch < 2; ch++) {
            uint32_t ah[2][4], al[2][4];
#pragma unroll
            for (int mi = 0; mi < 2; mi++) {
                uint32_t ar = (uint32_t)(wm + mi * 16 + (lane & 15));
                uint32_t ac = (uint32_t)(ch * 16 + ((lane >> 4) << 3));
                uint32_t aoff = (ar * ASTR + ac) * 2;
                ldm_x4(ah[mi], st + OAH * 2 + aoff);
                ldm_x4(al[mi], st + OAL * 2 + aoff);
            }
            uint32_t br = (uint32_t)(wn + (lane & 7) + ((lane & 16) >> 1));
            uint32_t bc = (uint32_t)(ch * 16 + (lane & 8));
#pragma unroll
            for (int njp = 0; njp < NJ / 2; njp++) {
                uint32_t boff = ((br + njp * 16) * ASTR + bc) * 2;
                uint32_t bh[4], bl[4];
                ldm_x4(bh, st + OBH * 2 + boff);
                ldm_x4(bl, st + OBL * 2 + boff);
#pragma unroll
                for (int mi = 0; mi < 2; mi++) {
                    mma16(c[mi][2 * njp], al[mi], bh[0], bh[1]);
                    mma16(c[mi][2 * njp], ah[mi], bl[0], bl[1]);
                    mma16(c[mi][2 * njp], ah[mi], bh[0], bh[1]);
                    mma16(c[mi][2 * njp + 1], al[mi], bh[2], bh[3]);
                    mma16(c[mi][2 * njp + 1], ah[mi], bl[2], bl[3]);
                    mma16(c[mi][2 * njp + 1], ah[mi], bh[2], bh[3]);
                }
            }
        }
    };

    const int T = K / BK;
    stage_in(0);
    for (int kt = 0; kt < T; kt++) {
        CP_WAIT0();
        __syncthreads();
        if (kt + 1 < T) stage_in(kt + 1);
        comp(kt & 1);
        __syncthreads();
    }

    // epilogue
#pragma unroll
    for (int mi = 0; mi < 2; mi++) {
#pragma unroll
        for (int nj = 0; nj < NJ; nj++) {
            int row0 = bm0 + wm + mi * 16 + (lane >> 2);
            int col = bn0 + wn + nj * 8 + (lane & 3) * 2;
            float v0 = c[mi][nj][0], v1 = c[mi][nj][1];
            float v2 = c[mi][nj][2], v3 = c[mi][nj][3];
            if (BIAS) {
                float bb0 = (col < Ntrue) ? bias[col] : 0.f;
                float bb1 = (col + 1 < Ntrue) ? bias[col + 1] : 0.f;
                v0 += bb0; v1 += bb1; v2 += bb0; v3 += bb1;
            }
            if (RELU) {
                v0 = fmaxf(v0, 0.f); v1 = fmaxf(v1, 0.f);
                v2 = fmaxf(v2, 0.f); v3 = fmaxf(v3, 0.f);
            }
            if (OUTP) {
                float h0, l0, h1, l1;
                if (row0 < M) {
                    split1(v0, h0, l0); split1(v1, h1, l1);
                    *(__nv_bfloat162*)(Chi + (size_t)row0 * Npad + col) = __floats2bfloat162_rn(h0, h1);
                    *(__nv_bfloat162*)(Clo + (size_t)row0 * Npad + col) = __floats2bfloat162_rn(l0, l1);
                }
                if (row0 + 8 < M) {
                    split1(v2, h0, l0); split1(v3, h1, l1);
                    *(__nv_bfloat162*)(Chi + (size_t)(row0 + 8) * Npad + col) = __floats2bfloat162_rn(h0, h1);
                    *(__nv_bfloat162*)(Clo + (size_t)(row0 + 8) * Npad + col) = __floats2bfloat162_rn(l0, l1);
                }
            } else {
                if (row0 < M)
                    *(float2*)&Cf[(size_t)row0 * Npad + col] = make_float2(v0, v1);
                if (row0 + 8 < M)
                    *(float2*)&Cf[(size_t)(row0 + 8) * Npad + col] = make_float2(v2, v3);
            }
        }
    }
}

// ---------------- GCN propagation: fp32 in, bf16 planes out --------------------
template <int C4>
__global__ void k_agg4p(const float* __restrict__ h,
                        __nv_bfloat16* __restrict__ phi, __nv_bfloat16* __restrict__ plo) {
    int v = blockIdx.x * 8 + (threadIdx.x >> 5);
    if (v >= NN) return;
    int lane = threadIdx.x & 31;
    constexpr int F = C4 * 128;
    float dv = g_dinv[v];
    const float4* hv = (const float4*)(h + (size_t)v * F);
    float4 acc[C4];
    float s2 = dv * dv;
#pragma unroll
    for (int i = 0; i < C4; i++) {
        float4 t = hv[lane + i * 32];
        acc[i] = make_float4(t.x * s2, t.y * s2, t.z * s2, t.w * s2);
    }
    int e = g_rowptr[v], end = g_rowptr[v + 1];
#pragma unroll 4
    for (; e < end; e++) {
        int s = g_colsrc[e];
        if ((unsigned)s >= NN) continue;
        float nrm = dv * g_dinv[s];
        const float4* hs = (const float4*)(h + (size_t)s * F);
#pragma unroll
        for (int i = 0; i < C4; i++) {
            float4 t = hs[lane + i * 32];
            acc[i].x += nrm * t.x; acc[i].y += nrm * t.y;
            acc[i].z += nrm * t.z; acc[i].w += nrm * t.w;
        }
    }
#pragma unroll
    for (int i = 0; i < C4; i++) {
        int base = 4 * (lane + i * 32);
        float hx, lx, hy, ly, hz, lz, hw, lw;
        split1(acc[i].x, hx, lx); split1(acc[i].y, hy, ly);
        split1(acc[i].z, hz, lz); split1(acc[i].w, hw, lw);
        *(__nv_bfloat162*)(phi + (size_t)v * F + base)     = __floats2bfloat162_rn(hx, hy);
        *(__nv_bfloat162*)(phi + (size_t)v * F + base + 2) = __floats2bfloat162_rn(hz, hw);
        *(__nv_bfloat162*)(plo + (size_t)v * F + base)     = __floats2bfloat162_rn(lx, ly);
        *(__nv_bfloat162*)(plo + (size_t)v * F + base + 2) = __floats2bfloat162_rn(lz, lw);
    }
}

// ---------------- fused final aggregation + bias + softmax ---------------------
__global__ void k_agg_soft(const float* __restrict__ h, const float* __restrict__ b,
                           float* __restrict__ out) {
    int v = blockIdx.x * 8 + (threadIdx.x >> 5);
    if (v >= NN) return;
    int lane = threadIdx.x & 31;
    float dv = g_dinv[v];
    float2 a = ((const float2*)(h + (size_t)v * 64))[lane];
    float s2 = dv * dv;
    a.x *= s2; a.y *= s2;
    int e = g_rowptr[v], end = g_rowptr[v + 1];
#pragma unroll 4
    for (; e < end; e++) {
        int s = g_colsrc[e];
        if ((unsigned)s >= NN) continue;
        float nrm = dv * g_dinv[s];
        float2 t = ((const float2*)(h + (size_t)s * 64))[lane];
        a.x += nrm * t.x; a.y += nrm * t.y;
    }
    int c0 = 2 * lane, c1 = 2 * lane + 1;
    float v0 = (c0 < 50) ? (a.x + b[c0]) : -1e30f;
    float v1 = (c1 < 50) ? (a.y + b[c1]) : -1e30f;
    float m = fmaxf(v0, v1);
#pragma unroll
    for (int off = 16; off >= 1; off >>= 1)
        m = fmaxf(m, __shfl_xor_sync(0xffffffffu, m, off));
    float e0 = (c0 < 50) ? __expf(v0 - m) : 0.f;
    float e1 = (c1 < 50) ? __expf(v1 - m) : 0.f;
    float s = e0 + e1;
#pragma unroll
    for (int off = 16; off >= 1; off >>= 1)
        s += __shfl_xor_sync(0xffffffffu, s, off);
    float inv = 1.0f / s;
    if (c0 < 50) out[(size_t)v * 50 + c0] = e0 * inv;
    if (c1 < 50) out[(size_t)v * 50 + c1] = e1 * inv;
}

// ---------------- launch ------------------------------------------------------
static inline void* sym(const void* s) {
    void* p = nullptr;
    cudaGetSymbolAddress(&p, s);
    return p;
}

extern "C" void kernel_launch(void* const* d_in, const int* in_sizes, int n_in,
                              void* d_out, int out_size) {
    const float* x   = (const float*)d_in[0];
    const int*   ei  = (const int*)d_in[1];
    const float* w1  = (const float*)d_in[2];
    const float* b1  = (const float*)d_in[3];
    const float* w2  = (const float*)d_in[4];
    const float* b2  = (const float*)d_in[5];
    const float* w3  = (const float*)d_in[6];
    const float* b3  = (const float*)d_in[7];
    const float* g1w = (const float*)d_in[8];
    const float* g1b = (const float*)d_in[9];
    const float* g2w = (const float*)d_in[10];
    const float* g2b = (const float*)d_in[11];
    const float* g3w = (const float*)d_in[12];
    const float* g3b = (const float*)d_in[13];
    float* out = (float*)d_out;

    float* h128 = (float*)sym(g_h128);
    float* h256 = (float*)sym(g_h256);
    float* t64  = (float*)sym(g_t64);

    __nv_bfloat16* h64h = (__nv_bfloat16*)sym(g_h64h);
    __nv_bfloat16* h64l = (__nv_bfloat16*)sym(g_h64l);
    __nv_bfloat16* p128h = (__nv_bfloat16*)sym(g_p128h);
    __nv_bfloat16* p128l = (__nv_bfloat16*)sym(g_p128l);
    __nv_bfloat16* p256h = (__nv_bfloat16*)sym(g_p256h);
    __nv_bfloat16* p256l = (__nv_bfloat16*)sym(g_p256l);
    __nv_bfloat16* h512h = (__nv_bfloat16*)sym(g_h512h);
    __nv_bfloat16* h512l = (__nv_bfloat16*)sym(g_h512l);

    __nv_bfloat16* w3h = (__nv_bfloat16*)sym(g_w3h);
    __nv_bfloat16* w3l = (__nv_bfloat16*)sym(g_w3l);
    __nv_bfloat16* g1h = (__nv_bfloat16*)sym(g_g1h);
    __nv_bfloat16* g1l = (__nv_bfloat16*)sym(g_g1l);
    __nv_bfloat16* g2h = (__nv_bfloat16*)sym(g_g2h);
    __nv_bfloat16* g2l = (__nv_bfloat16*)sym(g_g2l);
    __nv_bfloat16* g3h = (__nv_bfloat16*)sym(g_g3h);
    __nv_bfloat16* g3l = (__nv_bfloat16*)sym(g_g3l);

    const int dyn128 = (2 * 128 * 40 + 2 * 128 * 40) * 2 * 2;  // 81920
    const int dyn64  = (2 * 128 * 40 + 2 * 64 * 40) * 2 * 2;   // 61440

    static cudaStream_t s1 = nullptr;
    static cudaEvent_t eFork = nullptr, eCsr = nullptr;
    static int init_done = 0;
    if (!init_done) {
        cudaFuncSetAttribute(k_gemm_bf<128, true, true, false>,
                             cudaFuncAttributeMaxDynamicSharedMemorySize, dyn128);
        cudaFuncSetAttribute(k_gemm_bf<128, true, true, true>,
                             cudaFuncAttributeMaxDynamicSharedMemorySize, dyn128);
        cudaFuncSetAttribute(k_gemm_bf<64, false, false, false>,
                             cudaFuncAttributeMaxDynamicSharedMemorySize, dyn64);
        cudaStreamCreateWithFlags(&s1, cudaStreamNonBlocking);
        cudaEventCreateWithFlags(&eFork, cudaEventDisableTiming);
        cudaEventCreateWithFlags(&eCsr, cudaEventDisableTiming);
        init_done = 1;
    }

    // fork point
    cudaEventRecord(eFork, 0);
    cudaStreamWaitEvent(s1, eFork, 0);

    // ---- default stream: fused MLP + weight splits (submission #1-#6) ----
    k_mlp12<<<(NN + 255) / 256, 256>>>(x, w1, b1, w2, b2, h64h, h64l);        // #1
    k_split_t<<<(64 * 128 + 255) / 256, 256>>>(w3, w3h, w3l, 64, 128);        // #2
    k_split_t<<<(128 * 256 + 255) / 256, 256>>>(g1w, g1h, g1l, 128, 256);     // #3
    k_split_t<<<(256 * 512 + 255) / 256, 256>>>(g2w, g2h, g2l, 256, 512);     // #4
    k_split_t<<<(512 * 50 + 255) / 256, 256>>>(g3w, g3h, g3l, 512, 50);       // #5
    k_gemm_bf<128, true, true, false><<<dim3(MB_ALL, 1), 256, dyn128>>>(      // #6 <- profiled
        h64h, h64l, w3h, w3l, b3, h128, nullptr, nullptr, NN, 64, 128, 128);

    // ---- s1: degree + CSR (overlaps MLP chain) ----
    k_zero_cnt<<<(NN + 255) / 256, 256, 0, s1>>>();
    k_count<<<(NE + 255) / 256, 256, 0, s1>>>(ei);
    k_scan1<<<NBLK, 1024, 0, s1>>>();
    k_scan2<<<1, 64, 0, s1>>>();
    k_scan3<<<(NN + 255) / 256, 256, 0, s1>>>();
    k_scatter<<<(NE + 255) / 256, 256, 0, s1>>>(ei);
    cudaEventRecord(eCsr, s1);

    // join
    cudaStreamWaitEvent(0, eCsr, 0);

    // GCN1
    k_agg4p<1><<<(NN + 7) / 8, 256>>>(h128, p128h, p128l);
    k_gemm_bf<128, true, true, false><<<dim3(MB_ALL, 2), 256, dyn128>>>(
        p128h, p128l, g1h, g1l, g1b, h256, nullptr, nullptr, NN, 128, 256, 256);

    // GCN2
    k_agg4p<2><<<(NN + 7) / 8, 256>>>(h256, p256h, p256l);
    k_gemm_bf<128, true, true, true><<<dim3(MB_ALL, 4), 256, dyn128>>>(
        p256h, p256l, g2h, g2l, g2b, nullptr, h512h, h512l, NN, 256, 512, 512);

    // GCN3: 512->50 (pad 64), then fused propagate+softmax
    k_gemm_bf<64, false, false, false><<<dim3(MB_ALL, 1), 256, dyn64>>>(
        h512h, h512l, g3h, g3l, nullptr, t64, nullptr, nullptr, NN, 512, 50, 64);
    k_agg_soft<<<(NN + 7) / 8, 256>>>(t64, g3b, out);
}

// round 14
// speedup vs baseline: 1.0142x; 1.0142x over previous
#include <cuda_runtime.h>
#include <cuda_bf16.h>
#include <math.h>
#include <stdint.h>

#define NN 50000
#define NE 800000
#define NBLK ((NN + 1023) / 1024)
#define MB_ALL 391

// ---------------- scratch (static device globals; no allocation) -------------
__device__ int   g_cnt[NN];
__device__ int   g_rowptr[NN + 1];
__device__ int   g_cursor[NN];
__device__ int   g_colsrc[NE];
__device__ int   g_bsum[64];
__device__ float g_dinv[NN];

__device__ float g_h128[(size_t)NN * 128];
__device__ float g_h256[(size_t)NN * 256];
__device__ float g_t64 [(size_t)NN * 64];

__device__ __align__(256) __nv_bfloat16 g_h64h [(size_t)NN * 64],  g_h64l [(size_t)NN * 64];
__device__ __align__(256) __nv_bfloat16 g_p128h[(size_t)NN * 128], g_p128l[(size_t)NN * 128];
__device__ __align__(256) __nv_bfloat16 g_p256h[(size_t)NN * 256], g_p256l[(size_t)NN * 256];
__device__ __align__(256) __nv_bfloat16 g_h512h[(size_t)NN * 512], g_h512l[(size_t)NN * 512];

__device__ __align__(256) __nv_bfloat16 g_w3h[128 * 64],  g_w3l[128 * 64];
__device__ __align__(256) __nv_bfloat16 g_g1h[256 * 128], g_g1l[256 * 128];
__device__ __align__(256) __nv_bfloat16 g_g2h[512 * 256], g_g2l[512 * 256];
__device__ __align__(256) __nv_bfloat16 g_g3h[50 * 512],  g_g3l[50 * 512];

// ---------------- helpers ------------------------------------------------------
__device__ __forceinline__ void split1(float x, float& hi, float& lo) {
    __nv_bfloat16 h = __float2bfloat16(x);
    hi = __bfloat162float(h);
    lo = x - hi;
}
__device__ __forceinline__ void mma16(float c[4], const uint32_t a[4], uint32_t b0, uint32_t b1) {
    asm("mma.sync.aligned.m16n8k16.row.col.f32.bf16.bf16.f32 "
        "{%0,%1,%2,%3},{%4,%5,%6,%7},{%8,%9},{%0,%1,%2,%3};"
        : "+f"(c[0]), "+f"(c[1]), "+f"(c[2]), "+f"(c[3])
        : "r"(a[0]), "r"(a[1]), "r"(a[2]), "r"(a[3]), "r"(b0), "r"(b1));
}
__device__ __forceinline__ void ldm_x4(uint32_t r[4], uint32_t saddr) {
    asm volatile("ldmatrix.sync.aligned.m8n8.x4.shared.b16 {%0,%1,%2,%3}, [%4];"
        : "=r"(r[0]), "=r"(r[1]), "=r"(r[2]), "=r"(r[3]) : "r"(saddr));
}
__device__ __forceinline__ uint32_t smem_u32(const void* p) {
    uint32_t a;
    asm("{ .reg .u64 t; cvta.to.shared.u64 t, %1; cvt.u32.u64 %0, t; }" : "=r"(a) : "l"(p));
    return a;
}
__device__ __forceinline__ void cpa16(uint32_t dst, const void* src, bool pred) {
    int sz = pred ? 16 : 0;
    asm volatile("cp.async.cg.shared.global [%0], [%1], 16, %2;"
        :: "r"(dst), "l"(src), "r"(sz));
}
#define CP_COMMIT() asm volatile("cp.async.commit_group;")
#define CP_WAIT0()  asm volatile("cp.async.wait_group 0;")

// ---------------- degree / CSR build -----------------------------------------
__global__ void k_zero_cnt() {
    int i = blockIdx.x * blockDim.x + threadIdx.x;
    if (i < NN) g_cnt[i] = 0;
}
__global__ void k_count(const int* __restrict__ ei) {
    int e = blockIdx.x * blockDim.x + threadIdx.x;
    if (e < NE) {
        int dst = ei[NE + e];
        if ((unsigned)dst < NN) atomicAdd(&g_cnt[dst], 1);
    }
}
__global__ void k_scan1() {
    __shared__ int sh[1024];
    int tid = threadIdx.x;
    int i = blockIdx.x * 1024 + tid;
    int v = (i < NN) ? g_cnt[i] : 0;
    if (i < NN) g_dinv[i] = rsqrtf((float)v + 1.0f);
    sh[tid] = v;
    __syncthreads();
    for (int off = 1; off < 1024; off <<= 1) {
        int t = (tid >= off) ? sh[tid - off] : 0;
        __syncthreads();
        sh[tid] += t;
        __syncthreads();
    }
    if (i < NN) g_rowptr[i] = sh[tid] - v;
    if (tid == 1023) g_bsum[blockIdx.x] = sh[1023];
}
__global__ void k_scan2() {
    __shared__ int sh[64];
    int tid = threadIdx.x;
    int v = (tid < NBLK) ? g_bsum[tid] : 0;
    sh[tid] = v;
    __syncthreads();
    for (int off = 1; off < 64; off <<= 1) {
        int t = (tid >= off) ? sh[tid - off] : 0;
        __syncthreads();
        sh[tid] += t;
        __syncthreads();
    }
    g_bsum[tid] = sh[tid] - v;
}
__global__ void k_scan3() {
    int i = blockIdx.x * blockDim.x + threadIdx.x;
    if (i < NN) {
        int r = g_rowptr[i] + g_bsum[i >> 10];
        g_rowptr[i] = r;
        g_cursor[i] = r;
    }
    if (i == 0) g_rowptr[NN] = NE;
}
__global__ void k_scatter(const int* __restrict__ ei) {
    int e = blockIdx.x * blockDim.x + threadIdx.x;
    if (e < NE) {
        int dst = ei[NE + e];
        int src = ei[e];
        if ((unsigned)dst < NN && (unsigned)src < NN) {
            int pos = atomicAdd(&g_cursor[dst], 1);
            if ((unsigned)pos < NE) g_colsrc[pos] = src;
        }
    }
}

// ---------------- weight split + transpose -------------------------------------
__global__ void k_split_t(const float* __restrict__ src, __nv_bfloat16* __restrict__ hi,
                          __nv_bfloat16* __restrict__ lo, int K, int N) {
    int i = blockIdx.x * blockDim.x + threadIdx.x;
    if (i < K * N) {
        int k = i / N, n = i % N;
        float x = src[i];
        float h, l;
        split1(x, h, l);
        hi[(size_t)n * K + k] = __float2bfloat16(h);
        lo[(size_t)n * K + k] = __float2bfloat16(l);
    }
}

// ---------------- fused MLP1+MLP2 (3 -> 32 -> 64), writes h64 planes ----------
__global__ __launch_bounds__(256)
void k_mlp12(const float* __restrict__ x,
             const float* __restrict__ w1, const float* __restrict__ b1,
             const float* __restrict__ w2, const float* __restrict__ b2,
             __nv_bfloat16* __restrict__ hh, __nv_bfloat16* __restrict__ hl) {
    __shared__ float sw1[96], sb1[32], sw2[32 * 64], sb2[64];
    int tid = threadIdx.x;
    if (tid < 96) sw1[tid] = w1[tid];
    if (tid < 32) sb1[tid] = b1[tid];
    if (tid < 64) sb2[tid] = b2[tid];
    for (int i = tid; i < 32 * 64; i += 256) sw2[i] = w2[i];
    __syncthreads();

    int v = blockIdx.x * 256 + tid;
    if (v >= NN) return;
    float x0 = x[3 * v], x1 = x[3 * v + 1], x2 = x[3 * v + 2];

    float h32[32];
#pragma unroll
    for (int j = 0; j < 32; j++)
        h32[j] = fmaxf(x0 * sw1[j] + x1 * sw1[32 + j] + x2 * sw1[64 + j] + sb1[j], 0.f);

    __nv_bfloat162* ph = (__nv_bfloat162*)(hh + (size_t)v * 64);
    __nv_bfloat162* pl = (__nv_bfloat162*)(hl + (size_t)v * 64);
#pragma unroll 4
    for (int j = 0; j < 64; j += 2) {
        float a0 = sb2[j], a1 = sb2[j + 1];
#pragma unroll
        for (int k = 0; k < 32; k++) {
            float hk = h32[k];
            a0 += hk * sw2[k * 64 + j];
            a1 += hk * sw2[k * 64 + j + 1];
        }
        a0 = fmaxf(a0, 0.f);
        a1 = fmaxf(a1, 0.f);
        float h0, l0, h1, l1;
        split1(a0, h0, l0);
        split1(a1, h1, l1);
        ph[j >> 1] = __floats2bfloat162_rn(h0, h1);
        pl[j >> 1] = __floats2bfloat162_rn(l0, l1);
    }
}

// ---------------- bf16x3 tensor-core GEMM (cp.async staging) -------------------
template <int BN, bool RELU, bool BIAS, bool OUTP>
__global__ __launch_bounds__(256)
void k_gemm_bf(const __nv_bfloat16* __restrict__ Ahi, const __nv_bfloat16* __restrict__ Alo,
               const __nv_bfloat16* __restrict__ Whi, const __nv_bfloat16* __restrict__ Wlo,
               const float* __restrict__ bias,
               float* __restrict__ Cf,
               __nv_bfloat16* __restrict__ Chi, __nv_bfloat16* __restrict__ Clo,
               int M, int K, int Ntrue, int Npad) {
    constexpr int BM = 128, BK = 32, ASTR = 40;
    constexpr int A_H = BM * ASTR;
    constexpr int B_H = BN * ASTR;
    constexpr int STAGE = 2 * A_H + 2 * B_H;
    constexpr int OAH = 0, OAL = A_H, OBH = 2 * A_H, OBL = 2 * A_H + B_H;
    constexpr int NJ = (BN / 2) / 8;
    constexpr int TPN = 256 / BN;
    constexpr int KSEG = BK / TPN;
    constexpr int NV = KSEG / 8;

    extern __shared__ __nv_bfloat16 sm[];
    const uint32_t smb = smem_u32(sm);
    int tid = threadIdx.x, lane = tid & 31, wid = tid >> 5;
    int wm = (wid & 3) * 32, wn = (wid >> 2) * (BN / 2);
    int bm0 = blockIdx.x * BM, bn0 = blockIdx.y * BN;

    float c[2][NJ][4];
#pragma unroll
    for (int mi = 0; mi < 2; mi++)
#pragma unroll
        for (int nj = 0; nj < NJ; nj++)
#pragma unroll
            for (int r = 0; r < 4; r++) c[mi][nj][r] = 0.f;

    int arow = tid >> 1, ahalf = tid & 1;
    int brow = tid / TPN, bseg = tid % TPN;
    bool aok = (bm0 + arow) < M;
    bool bok = (bn0 + brow) < Ntrue;
    const __nv_bfloat16* pAh = Ahi + (size_t)(bm0 + arow) * K + ahalf * 16;
    const __nv_bfloat16* pAl = Alo + (size_t)(bm0 + arow) * K + ahalf * 16;
    const __nv_bfloat16* pBh = Whi + (size_t)(bn0 + brow) * K + bseg * KSEG;
    const __nv_bfloat16* pBl = Wlo + (size_t)(bn0 + brow) * K + bseg * KSEG;
    uint32_t dA = smb + ((uint32_t)arow * ASTR + ahalf * 16) * 2;
    uint32_t dB = smb + ((uint32_t)brow * ASTR + bseg * KSEG) * 2;

    auto stage_in = [&](int kt) {
        int k0 = kt * BK;
        uint32_t so = (uint32_t)((kt & 1) * STAGE) * 2;
        cpa16(so + dA + OAH * 2,      pAh + k0,     aok);
        cpa16(so + dA + OAH * 2 + 16, pAh + k0 + 8, aok);
        cpa16(so + dA + OAL * 2,      pAl + k0,     aok);
        cpa16(so + dA + OAL * 2 + 16, pAl + k0 + 8, aok);
#pragma unroll
        for (int v = 0; v < NV; v++) {
            cpa16(so + dB + OBH * 2 + v * 16, pBh + k0 + v * 8, bok);
            cpa16(so + dB + OBL * 2 + v * 16, pBl + k0 + v * 8, bok);
        }
        CP_COMMIT();
    };

    auto comp = [&](int buf) {
        uint32_t st = smb + (uint32_t)(buf * STAGE) * 2;
#pragma unroll
        for (int ch = 0; ch < 2; ch++) {
            uint32_t ah[2][4], al[2][4];
#pragma unroll
            for (int mi = 0; mi < 2; mi++) {
                uint32_t ar = (uint32_t)(wm + mi * 16 + (lane & 15));
                uint32_t ac = (uint32_t)(ch * 16 + ((lane >> 4) << 3));
                uint32_t aoff = (ar * ASTR + ac) * 2;
                ldm_x4(ah[mi], st + OAH * 2 + aoff);
                ldm_x4(al[mi], st + OAL * 2 + aoff);
            }
            uint32_t br = (uint32_t)(wn + (lane & 7) + ((lane & 16) >> 1));
            uint32_t bc = (uint32_t)(ch * 16 + (lane & 8));
#pragma unroll
            for (int njp = 0; njp < NJ / 2; njp++) {
                uint32_t boff = ((br + njp * 16) * ASTR + bc) * 2;
                uint32_t bh[4], bl[4];
                ldm_x4(bh, st + OBH * 2 + boff);
                ldm_x4(bl, st + OBL * 2 + boff);
#pragma unroll
                for (int mi = 0; mi < 2; mi++) {
                    mma16(c[mi][2 * njp], al[mi], bh[0], bh[1]);
                    mma16(c[mi][2 * njp], ah[mi], bl[0], bl[1]);
                    mma16(c[mi][2 * njp], ah[mi], bh[0], bh[1]);
                    mma16(c[mi][2 * njp + 1], al[mi], bh[2], bh[3]);
                    mma16(c[mi][2 * njp + 1], ah[mi], bl[2], bl[3]);
                    mma16(c[mi][2 * njp + 1], ah[mi], bh[2], bh[3]);
                }
            }
        }
    };

    const int T = K / BK;
    stage_in(0);
    for (int kt = 0; kt < T; kt++) {
        CP_WAIT0();
        __syncthreads();
        if (kt + 1 < T) stage_in(kt + 1);
        comp(kt & 1);
        __syncthreads();
    }

    // epilogue
#pragma unroll
    for (int mi = 0; mi < 2; mi++) {
#pragma unroll
        for (int nj = 0; nj < NJ; nj++) {
            int row0 = bm0 + wm + mi * 16 + (lane >> 2);
            int col = bn0 + wn + nj * 8 + (lane & 3) * 2;
            float v0 = c[mi][nj][0], v1 = c[mi][nj][1];
            float v2 = c[mi][nj][2], v3 = c[mi][nj][3];
            if (BIAS) {
                float bb0 = (col < Ntrue) ? bias[col] : 0.f;
                float bb1 = (col + 1 < Ntrue) ? bias[col + 1] : 0.f;
                v0 += bb0; v1 += bb1; v2 += bb0; v3 += bb1;
            }
            if (RELU) {
                v0 = fmaxf(v0, 0.f); v1 = fmaxf(v1, 0.f);
                v2 = fmaxf(v2, 0.f); v3 = fmaxf(v3, 0.f);
            }
            if (OUTP) {
                float h0, l0, h1, l1;
                if (row0 < M) {
                    split1(v0, h0, l0); split1(v1, h1, l1);
                    *(__nv_bfloat162*)(Chi + (size_t)row0 * Npad + col) = __floats2bfloat162_rn(h0, h1);
                    *(__nv_bfloat162*)(Clo + (size_t)row0 * Npad + col) = __floats2bfloat162_rn(l0, l1);
                }
                if (row0 + 8 < M) {
                    split1(v2, h0, l0); split1(v3, h1, l1);
                    *(__nv_bfloat162*)(Chi + (size_t)(row0 + 8) * Npad + col) = __floats2bfloat162_rn(h0, h1);
                    *(__nv_bfloat162*)(Clo + (size_t)(row0 + 8) * Npad + col) = __floats2bfloat162_rn(l0, l1);
                }
            } else {
                if (row0 < M)
                    *(float2*)&Cf[(size_t)row0 * Npad + col] = make_float2(v0, v1);
                if (row0 + 8 < M)
                    *(float2*)&Cf[(size_t)(row0 + 8) * Npad + col] = make_float2(v2, v3);
            }
        }
    }
}

// ---------------- GCN propagation: fp32 in, bf16 planes out --------------------
template <int C4>
__global__ void k_agg4p(const float* __restrict__ h,
                        __nv_bfloat16* __restrict__ phi, __nv_bfloat16* __restrict__ plo) {
    int v = blockIdx.x * 8 + (threadIdx.x >> 5);
    if (v >= NN) return;
    int lane = threadIdx.x & 31;
    constexpr int F = C4 * 128;
    float dv = g_dinv[v];
    const float4* hv = (const float4*)(h + (size_t)v * F);
    float4 acc[C4];
    float s2 = dv * dv;
#pragma unroll
    for (int i = 0; i < C4; i++) {
        float4 t = hv[lane + i * 32];
        acc[i] = make_float4(t.x * s2, t.y * s2, t.z * s2, t.w * s2);
    }
    int e = g_rowptr[v], end = g_rowptr[v + 1];
#pragma unroll 4
    for (; e < end; e++) {
        int s = g_colsrc[e];
        if ((unsigned)s >= NN) continue;
        float nrm = dv * g_dinv[s];
        const float4* hs = (const float4*)(h + (size_t)s * F);
#pragma unroll
        for (int i = 0; i < C4; i++) {
            float4 t = hs[lane + i * 32];
            acc[i].x += nrm * t.x; acc[i].y += nrm * t.y;
            acc[i].z += nrm * t.z; acc[i].w += nrm * t.w;
        }
    }
#pragma unroll
    for (int i = 0; i < C4; i++) {
        int base = 4 * (lane + i * 32);
        float hx, lx, hy, ly, hz, lz, hw, lw;
        split1(acc[i].x, hx, lx); split1(acc[i].y, hy, ly);
        split1(acc[i].z, hz, lz); split1(acc[i].w, hw, lw);
        *(__nv_bfloat162*)(phi + (size_t)v * F + base)     = __floats2bfloat162_rn(hx, hy);
        *(__nv_bfloat162*)(phi + (size_t)v * F + base + 2) = __floats2bfloat162_rn(hz, hw);
        *(__nv_bfloat162*)(plo + (size_t)v * F + base)     = __floats2bfloat162_rn(lx, ly);
        *(__nv_bfloat162*)(plo + (size_t)v * F + base + 2) = __floats2bfloat162_rn(lz, lw);
    }
}

// ---------------- fused final aggregation + bias + softmax ---------------------
__global__ void k_agg_soft(const float* __restrict__ h, const float* __restrict__ b,
                           float* __restrict__ out) {
    int v = blockIdx.x * 8 + (threadIdx.x >> 5);
    if (v >= NN) return;
    int lane = threadIdx.x & 31;
    float dv = g_dinv[v];
    float2 a = ((const float2*)(h + (size_t)v * 64))[lane];
    float s2 = dv * dv;
    a.x *= s2; a.y *= s2;
    int e = g_rowptr[v], end = g_rowptr[v + 1];
#pragma unroll 4
    for (; e < end; e++) {
        int s = g_colsrc[e];
        if ((unsigned)s >= NN) continue;
        float nrm = dv * g_dinv[s];
        float2 t = ((const float2*)(h + (size_t)s * 64))[lane];
        a.x += nrm * t.x; a.y += nrm * t.y;
    }
    int c0 = 2 * lane, c1 = 2 * lane + 1;
    float v0 = (c0 < 50) ? (a.x + b[c0]) : -1e30f;
    float v1 = (c1 < 50) ? (a.y + b[c1]) : -1e30f;
    float m = fmaxf(v0, v1);
#pragma unroll
    for (int off = 16; off >= 1; off >>= 1)
        m = fmaxf(m, __shfl_xor_sync(0xffffffffu, m, off));
    float e0 = (c0 < 50) ? __expf(v0 - m) : 0.f;
    float e1 = (c1 < 50) ? __expf(v1 - m) : 0.f;
    float s = e0 + e1;
#pragma unroll
    for (int off = 16; off >= 1; off >>= 1)
        s += __shfl_xor_sync(0xffffffffu, s, off);
    float inv = 1.0f / s;
    if (c0 < 50) out[(size_t)v * 50 + c0] = e0 * inv;
    if (c1 < 50) out[(size_t)v * 50 + c1] = e1 * inv;
}

// ---------------- launch ------------------------------------------------------
static inline void* sym(const void* s) {
    void* p = nullptr;
    cudaGetSymbolAddress(&p, s);
    return p;
}

extern "C" void kernel_launch(void* const* d_in, const int* in_sizes, int n_in,
                              void* d_out, int out_size) {
    const float* x   = (const float*)d_in[0];
    const int*   ei  = (const int*)d_in[1];
    const float* w1  = (const float*)d_in[2];
    const float* b1  = (const float*)d_in[3];
    const float* w2  = (const float*)d_in[4];
    const float* b2  = (const float*)d_in[5];
    const float* w3  = (const float*)d_in[6];
    const float* b3  = (const float*)d_in[7];
    const float* g1w = (const float*)d_in[8];
    const float* g1b = (const float*)d_in[9];
    const float* g2w = (const float*)d_in[10];
    const float* g2b = (const float*)d_in[11];
    const float* g3w = (const float*)d_in[12];
    const float* g3b = (const float*)d_in[13];
    float* out = (float*)d_out;

    float* h128 = (float*)sym(g_h128);
    float* h256 = (float*)sym(g_h256);
    float* t64  = (float*)sym(g_t64);

    __nv_bfloat16* h64h = (__nv_bfloat16*)sym(g_h64h);
    __nv_bfloat16* h64l = (__nv_bfloat16*)sym(g_h64l);
    __nv_bfloat16* p128h = (__nv_bfloat16*)sym(g_p128h);
    __nv_bfloat16* p128l = (__nv_bfloat16*)sym(g_p128l);
    __nv_bfloat16* p256h = (__nv_bfloat16*)sym(g_p256h);
    __nv_bfloat16* p256l = (__nv_bfloat16*)sym(g_p256l);
    __nv_bfloat16* h512h = (__nv_bfloat16*)sym(g_h512h);
    __nv_bfloat16* h512l = (__nv_bfloat16*)sym(g_h512l);

    __nv_bfloat16* w3h = (__nv_bfloat16*)sym(g_w3h);
    __nv_bfloat16* w3l = (__nv_bfloat16*)sym(g_w3l);
    __nv_bfloat16* g1h = (__nv_bfloat16*)sym(g_g1h);
    __nv_bfloat16* g1l = (__nv_bfloat16*)sym(g_g1l);
    __nv_bfloat16* g2h = (__nv_bfloat16*)sym(g_g2h);
    __nv_bfloat16* g2l = (__nv_bfloat16*)sym(g_g2l);
    __nv_bfloat16* g3h = (__nv_bfloat16*)sym(g_g3h);
    __nv_bfloat16* g3l = (__nv_bfloat16*)sym(g_g3l);

    const int dyn128 = (2 * 128 * 40 + 2 * 128 * 40) * 2 * 2;  // 81920
    const int dyn64  = (2 * 128 * 40 + 2 * 64 * 40) * 2 * 2;   // 61440

    static cudaStream_t s1 = nullptr, s2 = nullptr;
    static cudaEvent_t eFork = nullptr, eCsr = nullptr, eWts = nullptr;
    static int init_done = 0;
    if (!init_done) {
        cudaFuncSetAttribute(k_gemm_bf<128, true, true, false>,
                             cudaFuncAttributeMaxDynamicSharedMemorySize, dyn128);
        cudaFuncSetAttribute(k_gemm_bf<128, true, true, true>,
                             cudaFuncAttributeMaxDynamicSharedMemorySize, dyn128);
        cudaFuncSetAttribute(k_gemm_bf<64, false, false, false>,
                             cudaFuncAttributeMaxDynamicSharedMemorySize, dyn64);
        cudaStreamCreateWithFlags(&s1, cudaStreamNonBlocking);
        cudaStreamCreateWithFlags(&s2, cudaStreamNonBlocking);
        cudaEventCreateWithFlags(&eFork, cudaEventDisableTiming);
        cudaEventCreateWithFlags(&eCsr, cudaEventDisableTiming);
        cudaEventCreateWithFlags(&eWts, cudaEventDisableTiming);
        init_done = 1;
    }

    // fork point (events only — no kernels yet)
    cudaEventRecord(eFork, 0);
    cudaStreamWaitEvent(s1, eFork, 0);
    cudaStreamWaitEvent(s2, eFork, 0);

    // ---- default stream: fused MLP chain (submissions #1-#4) ----
    k_mlp12<<<(NN + 255) / 256, 256>>>(x, w1, b1, w2, b2, h64h, h64l);        // #1
    k_split_t<<<(64 * 128 + 255) / 256, 256>>>(w3, w3h, w3l, 64, 128);        // #2
    k_split_t<<<(512 * 50 + 255) / 256, 256>>>(g3w, g3h, g3l, 512, 50);       // #3
    k_gemm_bf<128, true, true, false><<<dim3(MB_ALL, 1), 256, dyn128>>>(      // #4
        h64h, h64l, w3h, w3l, b3, h128, nullptr, nullptr, NN, 64, 128, 128);

    // ---- s1: degree + CSR (overlaps MLP chain) ----
    k_zero_cnt<<<(NN + 255) / 256, 256, 0, s1>>>();
    k_count<<<(NE + 255) / 256, 256, 0, s1>>>(ei);
    k_scan1<<<NBLK, 1024, 0, s1>>>();
    k_scan2<<<1, 64, 0, s1>>>();
    k_scan3<<<(NN + 255) / 256, 256, 0, s1>>>();
    k_scatter<<<(NE + 255) / 256, 256, 0, s1>>>(ei);
    cudaEventRecord(eCsr, s1);

    // ---- s2: big GCN weight splits (overlap MLP chain) ----
    k_split_t<<<(128 * 256 + 255) / 256, 256, 0, s2>>>(g1w, g1h, g1l, 128, 256);
    k_split_t<<<(256 * 512 + 255) / 256, 256, 0, s2>>>(g2w, g2h, g2l, 256, 512);
    cudaEventRecord(eWts, s2);

    // join
    cudaStreamWaitEvent(0, eCsr, 0);
    cudaStreamWaitEvent(0, eWts, 0);

    // GCN1
    k_agg4p<1><<<(NN + 7) / 8, 256>>>(h128, p128h, p128l);
    k_gemm_bf<128, true, true, false><<<dim3(MB_ALL, 2), 256, dyn128>>>(
        p128h, p128l, g1h, g1l, g1b, h256, nullptr, nullptr, NN, 128, 256, 256);

    // GCN2
    k_agg4p<2><<<(NN + 7) / 8, 256>>>(h256, p256h, p256l);
    k_gemm_bf<128, true, true, true><<<dim3(MB_ALL, 4), 256, dyn128>>>(
        p256h, p256l, g2h, g2l, g2b, nullptr, h512h, h512l, NN, 256, 512, 512);

    // GCN3: 512->50 (pad 64), then fused propagate+softmax
    k_gemm_bf<64, false, false, false><<<dim3(MB_ALL, 1), 256, dyn64>>>(
        h512h, h512l, g3h, g3l, nullptr, t64, nullptr, nullptr, NN, 512, 50, 64);
    k_agg_soft<<<(NN + 7) / 8, 256>>>(t64, g3b, out);
}

// round 15
// speedup vs baseline: 1.0410x; 1.0263x over previous
#include <cuda_runtime.h>
#include <cuda_bf16.h>
#include <math.h>
#include <stdint.h>

#define NN 50000
#define NE 800000
#define NBLK ((NN + 1023) / 1024)

// ---------------- scratch (static device globals; no allocation) -------------
__device__ int   g_cnt[NN];
__device__ int   g_rowptr[NN + 1];
__device__ int   g_cursor[NN];
__device__ int   g_colsrc[NE];
__device__ int   g_bsum[64];
__device__ float g_dinv[NN];

__device__ float g_h128[(size_t)NN * 128];
__device__ float g_h256[(size_t)NN * 256];
__device__ float g_t64 [(size_t)NN * 64];

__device__ __align__(256) __nv_bfloat16 g_h32h [(size_t)NN * 32],  g_h32l [(size_t)NN * 32];
__device__ __align__(256) __nv_bfloat16 g_h64h [(size_t)NN * 64],  g_h64l [(size_t)NN * 64];
__device__ __align__(256) __nv_bfloat16 g_p128h[(size_t)NN * 128], g_p128l[(size_t)NN * 128];
__device__ __align__(256) __nv_bfloat16 g_p256h[(size_t)NN * 256], g_p256l[(size_t)NN * 256];
__device__ __align__(256) __nv_bfloat16 g_h512h[(size_t)NN * 512], g_h512l[(size_t)NN * 512];

__device__ __align__(256) __nv_bfloat16 g_w2h[64 * 32],   g_w2l[64 * 32];
__device__ __align__(256) __nv_bfloat16 g_w3h[128 * 64],  g_w3l[128 * 64];
__device__ __align__(256) __nv_bfloat16 g_g1h[256 * 128], g_g1l[256 * 128];
__device__ __align__(256) __nv_bfloat16 g_g2h[512 * 256], g_g2l[512 * 256];
__device__ __align__(256) __nv_bfloat16 g_g3h[50 * 512],  g_g3l[50 * 512];

// ---------------- helpers ------------------------------------------------------
__device__ __forceinline__ void split1(float x, float& hi, float& lo) {
    __nv_bfloat16 h = __float2bfloat16(x);
    hi = __bfloat162float(h);
    lo = x - hi;
}
__device__ __forceinline__ void mma16(float c[4], const uint32_t a[4], uint32_t b0, uint32_t b1) {
    asm("mma.sync.aligned.m16n8k16.row.col.f32.bf16.bf16.f32 "
        "{%0,%1,%2,%3},{%4,%5,%6,%7},{%8,%9},{%0,%1,%2,%3};"
        : "+f"(c[0]), "+f"(c[1]), "+f"(c[2]), "+f"(c[3])
        : "r"(a[0]), "r"(a[1]), "r"(a[2]), "r"(a[3]), "r"(b0), "r"(b1));
}
__device__ __forceinline__ void ldm_x4(uint32_t r[4], uint32_t saddr) {
    asm volatile("ldmatrix.sync.aligned.m8n8.x4.shared.b16 {%0,%1,%2,%3}, [%4];"
        : "=r"(r[0]), "=r"(r[1]), "=r"(r[2]), "=r"(r[3]) : "r"(saddr));
}
__device__ __forceinline__ uint32_t smem_u32(const void* p) {
    uint32_t a;
    asm("{ .reg .u64 t; cvta.to.shared.u64 t, %1; cvt.u32.u64 %0, t; }" : "=r"(a) : "l"(p));
    return a;
}
__device__ __forceinline__ void cpa16(uint32_t dst, const void* src, bool pred) {
    int sz = pred ? 16 : 0;
    asm volatile("cp.async.cg.shared.global [%0], [%1], 16, %2;"
        :: "r"(dst), "l"(src), "r"(sz));
}
#define CP_COMMIT() asm volatile("cp.async.commit_group;")
#define CP_WAIT0()  asm volatile("cp.async.wait_group 0;")

// ---------------- degree / CSR build -----------------------------------------
__global__ void k_zero_cnt() {
    int i = blockIdx.x * blockDim.x + threadIdx.x;
    if (i < NN) g_cnt[i] = 0;
}
__global__ void k_count(const int* __restrict__ ei) {
    int e = blockIdx.x * blockDim.x + threadIdx.x;
    if (e < NE) {
        int dst = ei[NE + e];
        if ((unsigned)dst < NN) atomicAdd(&g_cnt[dst], 1);
    }
}
__global__ void k_scan1() {
    __shared__ int sh[1024];
    int tid = threadIdx.x;
    int i = blockIdx.x * 1024 + tid;
    int v = (i < NN) ? g_cnt[i] : 0;
    if (i < NN) g_dinv[i] = rsqrtf((float)v + 1.0f);
    sh[tid] = v;
    __syncthreads();
    for (int off = 1; off < 1024; off <<= 1) {
        int t = (tid >= off) ? sh[tid - off] : 0;
        __syncthreads();
        sh[tid] += t;
        __syncthreads();
    }
    if (i < NN) g_rowptr[i] = sh[tid] - v;
    if (tid == 1023) g_bsum[blockIdx.x] = sh[1023];
}
__global__ void k_scan2() {
    __shared__ int sh[64];
    int tid = threadIdx.x;
    int v = (tid < NBLK) ? g_bsum[tid] : 0;
    sh[tid] = v;
    __syncthreads();
    for (int off = 1; off < 64; off <<= 1) {
        int t = (tid >= off) ? sh[tid - off] : 0;
        __syncthreads();
        sh[tid] += t;
        __syncthreads();
    }
    g_bsum[tid] = sh[tid] - v;
}
__global__ void k_scan3() {
    int i = blockIdx.x * blockDim.x + threadIdx.x;
    if (i < NN) {
        int r = g_rowptr[i] + g_bsum[i >> 10];
        g_rowptr[i] = r;
        g_cursor[i] = r;
    }
    if (i == 0) g_rowptr[NN] = NE;
}
__global__ void k_scatter(const int* __restrict__ ei) {
    int e = blockIdx.x * blockDim.x + threadIdx.x;
    if (e < NE) {
        int dst = ei[NE + e];
        int src = ei[e];
        if ((unsigned)dst < NN && (unsigned)src < NN) {
            int pos = atomicAdd(&g_cursor[dst], 1);
            if ((unsigned)pos < NE) g_colsrc[pos] = src;
        }
    }
}

// ---------------- weight split + transpose -------------------------------------
__global__ void k_split_t(const float* __restrict__ src, __nv_bfloat16* __restrict__ hi,
                          __nv_bfloat16* __restrict__ lo, int K, int N) {
    int i = blockIdx.x * blockDim.x + threadIdx.x;
    if (i < K * N) {
        int k = i / N, n = i % N;
        float x = src[i];
        float h, l;
        split1(x, h, l);
        hi[(size_t)n * K + k] = __float2bfloat16(h);
        lo[(size_t)n * K + k] = __float2bfloat16(l);
    }
}

// ---------------- MLP layer 1 (K=3 -> 32), writes planes ----------------------
__global__ __launch_bounds__(256)
void k_mlp1(const float* __restrict__ x, const float* __restrict__ w,
            const float* __restrict__ b,
            __nv_bfloat16* __restrict__ hh, __nv_bfloat16* __restrict__ hl) {
    __shared__ float sw[96], sb[32];
    int tid = threadIdx.x;
    if (tid < 96) sw[tid] = w[tid];
    if (tid < 32) sb[tid] = b[tid];
    __syncthreads();
    int v = blockIdx.x * 256 + tid;
    if (v >= NN) return;
    float x0 = x[3 * v], x1 = x[3 * v + 1], x2 = x[3 * v + 2];
    __nv_bfloat162* ph = (__nv_bfloat162*)(hh + (size_t)v * 32);
    __nv_bfloat162* pl = (__nv_bfloat162*)(hl + (size_t)v * 32);
#pragma unroll
    for (int j = 0; j < 32; j += 2) {
        float h0 = fmaxf(x0 * sw[j] + x1 * sw[32 + j] + x2 * sw[64 + j] + sb[j], 0.f);
        float h1 = fmaxf(x0 * sw[j + 1] + x1 * sw[32 + j + 1] + x2 * sw[64 + j + 1] + sb[j + 1], 0.f);
        float a0, l0, a1, l1;
        split1(h0, a0, l0);
        split1(h1, a1, l1);
        ph[j >> 1] = __floats2bfloat162_rn(a0, a1);
        pl[j >> 1] = __floats2bfloat162_rn(l0, l1);
    }
}

// ---------------- bf16x3 tensor-core GEMM (cp.async staging) -------------------
template <int BN, bool RELU, bool BIAS, bool OUTP>
__global__ __launch_bounds__(256)
void k_gemm_bf(const __nv_bfloat16* __restrict__ Ahi, const __nv_bfloat16* __restrict__ Alo,
               const __nv_bfloat16* __restrict__ Whi, const __nv_bfloat16* __restrict__ Wlo,
               const float* __restrict__ bias,
               float* __restrict__ Cf,
               __nv_bfloat16* __restrict__ Chi, __nv_bfloat16* __restrict__ Clo,
               int M, int K, int Ntrue, int Npad) {
    constexpr int BM = 128, BK = 32, ASTR = 40;
    constexpr int A_H = BM * ASTR;
    constexpr int B_H = BN * ASTR;
    constexpr int STAGE = 2 * A_H + 2 * B_H;
    constexpr int OAH = 0, OAL = A_H, OBH = 2 * A_H, OBL = 2 * A_H + B_H;
    constexpr int NJ = (BN / 2) / 8;
    constexpr int TPN = 256 / BN;
    constexpr int KSEG = BK / TPN;
    constexpr int NV = KSEG / 8;

    extern __shared__ __nv_bfloat16 sm[];
    const uint32_t smb = smem_u32(sm);
    int tid = threadIdx.x, lane = tid & 31, wid = tid >> 5;
    int wm = (wid & 3) * 32, wn = (wid >> 2) * (BN / 2);
    int bm0 = blockIdx.x * BM, bn0 = blockIdx.y * BN;

    float c[2][NJ][4];
#pragma unroll
    for (int mi = 0; mi < 2; mi++)
#pragma unroll
        for (int nj = 0; nj < NJ; nj++)
#pragma unroll
            for (int r = 0; r < 4; r++) c[mi][nj][r] = 0.f;

    int arow = tid >> 1, ahalf = tid & 1;
    int brow = tid / TPN, bseg = tid % TPN;
    bool aok = (bm0 + arow) < M;
    bool bok = (bn0 + brow) < Ntrue;
    const __nv_bfloat16* pAh = Ahi + (size_t)(bm0 + arow) * K + ahalf * 16;
    const __nv_bfloat16* pAl = Alo + (size_t)(bm0 + arow) * K + ahalf * 16;
    const __nv_bfloat16* pBh = Whi + (size_t)(bn0 + brow) * K + bseg * KSEG;
    const __nv_bfloat16* pBl = Wlo + (size_t)(bn0 + brow) * K + bseg * KSEG;
    uint32_t dA = smb + ((uint32_t)arow * ASTR + ahalf * 16) * 2;
    uint32_t dB = smb + ((uint32_t)brow * ASTR + bseg * KSEG) * 2;

    auto stage_in = [&](int kt) {
        int k0 = kt * BK;
        uint32_t so = (uint32_t)((kt & 1) * STAGE) * 2;
        cpa16(so + dA + OAH * 2,      pAh + k0,     aok);
        cpa16(so + dA + OAH * 2 + 16, pAh + k0 + 8, aok);
        cpa16(so + dA + OAL * 2,      pAl + k0,     aok);
        cpa16(so + dA + OAL * 2 + 16, pAl + k0 + 8, aok);
#pragma unroll
        for (int v = 0; v < NV; v++) {
            cpa16(so + dB + OBH * 2 + v * 16, pBh + k0 + v * 8, bok);
            cpa16(so + dB + OBL * 2 + v * 16, pBl + k0 + v * 8, bok);
        }
        CP_COMMIT();
    };

    auto comp = [&](int buf) {
        uint32_t st = smb + (uint32_t)(buf * STAGE) * 2;
#pragma unroll
        for (int ch = 0; ch < 2; ch++) {
            uint32_t ah[2][4], al[2][4];
#pragma unroll
            for (int mi = 0; mi < 2; mi++) {
                uint32_t ar = (uint32_t)(wm + mi * 16 + (lane & 15));
                uint32_t ac = (uint32_t)(ch * 16 + ((lane >> 4) << 3));
                uint32_t aoff = (ar * ASTR + ac) * 2;
                ldm_x4(ah[mi], st + OAH * 2 + aoff);
                ldm_x4(al[mi], st + OAL * 2 + aoff);
            }
            uint32_t br = (uint32_t)(wn + (lane & 7) + ((lane & 16) >> 1));
            uint32_t bc = (uint32_t)(ch * 16 + (lane & 8));
#pragma unroll
            for (int njp = 0; njp < NJ / 2; njp++) {
                uint32_t boff = ((br + njp * 16) * ASTR + bc) * 2;
                uint32_t bh[4], bl[4];
                ldm_x4(bh, st + OBH * 2 + boff);
                ldm_x4(bl, st + OBL * 2 + boff);
#pragma unroll
                for (int mi = 0; mi < 2; mi++) {
                    mma16(c[mi][2 * njp], al[mi], bh[0], bh[1]);
                    mma16(c[mi][2 * njp], ah[mi], bl[0], bl[1]);
                    mma16(c[mi][2 * njp], ah[mi], bh[0], bh[1]);
                    mma16(c[mi][2 * njp + 1], al[mi], bh[2], bh[3]);
                    mma16(c[mi][2 * njp + 1], ah[mi], bl[2], bl[3]);
                    mma16(c[mi][2 * njp + 1], ah[mi], bh[2], bh[3]);
                }
            }
        }
    };

    const int T = K / BK;
    stage_in(0);
    for (int kt = 0; kt < T; kt++) {
        CP_WAIT0();
        __syncthreads();
        if (kt + 1 < T) stage_in(kt + 1);
        comp(kt & 1);
        __syncthreads();
    }

    // epilogue
#pragma unroll
    for (int mi = 0; mi < 2; mi++) {
#pragma unroll
        for (int nj = 0; nj < NJ; nj++) {
            int row0 = bm0 + wm + mi * 16 + (lane >> 2);
            int col = bn0 + wn + nj * 8 + (lane & 3) * 2;
            float v0 = c[mi][nj][0], v1 = c[mi][nj][1];
            float v2 = c[mi][nj][2], v3 = c[mi][nj][3];
            if (BIAS) {
                float bb0 = (col < Ntrue) ? bias[col] : 0.f;
                float bb1 = (col + 1 < Ntrue) ? bias[col + 1] : 0.f;
                v0 += bb0; v1 += bb1; v2 += bb0; v3 += bb1;
            }
            if (RELU) {
                v0 = fmaxf(v0, 0.f); v1 = fmaxf(v1, 0.f);
                v2 = fmaxf(v2, 0.f); v3 = fmaxf(v3, 0.f);
            }
            if (OUTP) {
                float h0, l0, h1, l1;
                if (row0 < M) {
                    split1(v0, h0, l0); split1(v1, h1, l1);
                    *(__nv_bfloat162*)(Chi + (size_t)row0 * Npad + col) = __floats2bfloat162_rn(h0, h1);
                    *(__nv_bfloat162*)(Clo + (size_t)row0 * Npad + col) = __floats2bfloat162_rn(l0, l1);
                }
                if (row0 + 8 < M) {
                    split1(v2, h0, l0); split1(v3, h1, l1);
                    *(__nv_bfloat162*)(Chi + (size_t)(row0 + 8) * Npad + col) = __floats2bfloat162_rn(h0, h1);
                    *(__nv_bfloat162*)(Clo + (size_t)(row0 + 8) * Npad + col) = __floats2bfloat162_rn(l0, l1);
                }
            } else {
                if (row0 < M)
                    *(float2*)&Cf[(size_t)row0 * Npad + col] = make_float2(v0, v1);
                if (row0 + 8 < M)
                    *(float2*)&Cf[(size_t)(row0 + 8) * Npad + col] = make_float2(v2, v3);
            }
        }
    }
}

// ---------------- GCN propagation: fp32 in, bf16 planes out --------------------
template <int C4>
__global__ void k_agg4p(const float* __restrict__ h,
                        __nv_bfloat16* __restrict__ phi, __nv_bfloat16* __restrict__ plo) {
    int v = blockIdx.x * 8 + (threadIdx.x >> 5);
    if (v >= NN) return;
    int lane = threadIdx.x & 31;
    constexpr int F = C4 * 128;
    float dv = g_dinv[v];
    const float4* hv = (const float4*)(h + (size_t)v * F);
    float4 acc[C4];
    float s2 = dv * dv;
#pragma unroll
    for (int i = 0; i < C4; i++) {
        float4 t = hv[lane + i * 32];
        acc[i] = make_float4(t.x * s2, t.y * s2, t.z * s2, t.w * s2);
    }
    int e = g_rowptr[v], end = g_rowptr[v + 1];
    for (; e < end; e++) {
        int s = g_colsrc[e];
        if ((unsigned)s >= NN) continue;
        float nrm = dv * g_dinv[s];
        const float4* hs = (const float4*)(h + (size_t)s * F);
#pragma unroll
        for (int i = 0; i < C4; i++) {
            float4 t = hs[lane + i * 32];
            acc[i].x += nrm * t.x; acc[i].y += nrm * t.y;
            acc[i].z += nrm * t.z; acc[i].w += nrm * t.w;
        }
    }
#pragma unroll
    for (int i = 0; i < C4; i++) {
        int base = 4 * (lane + i * 32);
        float hx, lx, hy, ly, hz, lz, hw, lw;
        split1(acc[i].x, hx, lx); split1(acc[i].y, hy, ly);
        split1(acc[i].z, hz, lz); split1(acc[i].w, hw, lw);
        *(__nv_bfloat162*)(phi + (size_t)v * F + base)     = __floats2bfloat162_rn(hx, hy);
        *(__nv_bfloat162*)(phi + (size_t)v * F + base + 2) = __floats2bfloat162_rn(hz, hw);
        *(__nv_bfloat162*)(plo + (size_t)v * F + base)     = __floats2bfloat162_rn(lx, ly);
        *(__nv_bfloat162*)(plo + (size_t)v * F + base + 2) = __floats2bfloat162_rn(lz, lw);
    }
}

// ---------------- fused final aggregation + bias + softmax ---------------------
__global__ void k_agg_soft(const float* __restrict__ h, const float* __restrict__ b,
                           float* __restrict__ out) {
    int v = blockIdx.x * 8 + (threadIdx.x >> 5);
    if (v >= NN) return;
    int lane = threadIdx.x & 31;
    float dv = g_dinv[v];
    float2 a = ((const float2*)(h + (size_t)v * 64))[lane];
    float s2 = dv * dv;
    a.x *= s2; a.y *= s2;
    int e = g_rowptr[v], end = g_rowptr[v + 1];
    for (; e < end; e++) {
        int s = g_colsrc[e];
        if ((unsigned)s >= NN) continue;
        float nrm = dv * g_dinv[s];
        float2 t = ((const float2*)(h + (size_t)s * 64))[lane];
        a.x += nrm * t.x; a.y += nrm * t.y;
    }
    int c0 = 2 * lane, c1 = 2 * lane + 1;
    float v0 = (c0 < 50) ? (a.x + b[c0]) : -1e30f;
    float v1 = (c1 < 50) ? (a.y + b[c1]) : -1e30f;
    float m = fmaxf(v0, v1);
#pragma unroll
    for (int off = 16; off >= 1; off >>= 1)
        m = fmaxf(m, __shfl_xor_sync(0xffffffffu, m, off));
    float e0 = (c0 < 50) ? __expf(v0 - m) : 0.f;
    float e1 = (c1 < 50) ? __expf(v1 - m) : 0.f;
    float s = e0 + e1;
#pragma unroll
    for (int off = 16; off >= 1; off >>= 1)
        s += __shfl_xor_sync(0xffffffffu, s, off);
    float inv = 1.0f / s;
    if (c0 < 50) out[(size_t)v * 50 + c0] = e0 * inv;
    if (c1 < 50) out[(size_t)v * 50 + c1] = e1 * inv;
}

// ---------------- launch ------------------------------------------------------
static inline void* sym(const void* s) {
    void* p = nullptr;
    cudaGetSymbolAddress(&p, s);
    return p;
}

extern "C" void kernel_launch(void* const* d_in, const int* in_sizes, int n_in,
                              void* d_out, int out_size) {
    const float* x   = (const float*)d_in[0];
    const int*   ei  = (const int*)d_in[1];
    const float* w1  = (const float*)d_in[2];
    const float* b1  = (const float*)d_in[3];
    const float* w2  = (const float*)d_in[4];
    const float* b2  = (const float*)d_in[5];
    const float* w3  = (const float*)d_in[6];
    const float* b3  = (const float*)d_in[7];
    const float* g1w = (const float*)d_in[8];
    const float* g1b = (const float*)d_in[9];
    const float* g2w = (const float*)d_in[10];
    const float* g2b = (const float*)d_in[11];
    const float* g3w = (const float*)d_in[12];
    const float* g3b = (const float*)d_in[13];
    float* out = (float*)d_out;

    float* h128 = (float*)sym(g_h128);
    float* h256 = (float*)sym(g_h256);
    float* t64  = (float*)sym(g_t64);

    __nv_bfloat16* h32h = (__nv_bfloat16*)sym(g_h32h);
    __nv_bfloat16* h32l = (__nv_bfloat16*)sym(g_h32l);
    __nv_bfloat16* h64h = (__nv_bfloat16*)sym(g_h64h);
    __nv_bfloat16* h64l = (__nv_bfloat16*)sym(g_h64l);
    __nv_bfloat16* p128h = (__nv_bfloat16*)sym(g_p128h);
    __nv_bfloat16* p128l = (__nv_bfloat16*)sym(g_p128l);
    __nv_bfloat16* p256h = (__nv_bfloat16*)sym(g_p256h);
    __nv_bfloat16* p256l = (__nv_bfloat16*)sym(g_p256l);
    __nv_bfloat16* h512h = (__nv_bfloat16*)sym(g_h512h);
    __nv_bfloat16* h512l = (__nv_bfloat16*)sym(g_h512l);

    __nv_bfloat16* w2h = (__nv_bfloat16*)sym(g_w2h);
    __nv_bfloat16* w2l = (__nv_bfloat16*)sym(g_w2l);
    __nv_bfloat16* w3h = (__nv_bfloat16*)sym(g_w3h);
    __nv_bfloat16* w3l = (__nv_bfloat16*)sym(g_w3l);
    __nv_bfloat16* g1h = (__nv_bfloat16*)sym(g_g1h);
    __nv_bfloat16* g1l = (__nv_bfloat16*)sym(g_g1l);
    __nv_bfloat16* g2h = (__nv_bfloat16*)sym(g_g2h);
    __nv_bfloat16* g2l = (__nv_bfloat16*)sym(g_g2l);
    __nv_bfloat16* g3h = (__nv_bfloat16*)sym(g_g3h);
    __nv_bfloat16* g3l = (__nv_bfloat16*)sym(g_g3l);

    const int dyn128 = (2 * 128 * 40 + 2 * 128 * 40) * 2 * 2;  // 81920
    const int dyn64  = (2 * 128 * 40 + 2 * 64 * 40) * 2 * 2;   // 61440

    static cudaStream_t s1 = nullptr, s2 = nullptr;
    static cudaEvent_t eFork = nullptr, eCsr = nullptr, eWts = nullptr;
    static int init_done = 0;
    if (!init_done) {
        cudaFuncSetAttribute(k_gemm_bf<64, true, true, true>,
                             cudaFuncAttributeMaxDynamicSharedMemorySize, dyn64);
        cudaFuncSetAttribute(k_gemm_bf<128, true, true, false>,
                             cudaFuncAttributeMaxDynamicSharedMemorySize, dyn128);
        cudaFuncSetAttribute(k_gemm_bf<128, true, true, true>,
                             cudaFuncAttributeMaxDynamicSharedMemorySize, dyn128);
        cudaFuncSetAttribute(k_gemm_bf<64, false, false, false>,
                             cudaFuncAttributeMaxDynamicSharedMemorySize, dyn64);
        cudaStreamCreateWithFlags(&s1, cudaStreamNonBlocking);
        cudaStreamCreateWithFlags(&s2, cudaStreamNonBlocking);
        cudaEventCreateWithFlags(&eFork, cudaEventDisableTiming);
        cudaEventCreateWithFlags(&eCsr, cudaEventDisableTiming);
        cudaEventCreateWithFlags(&eWts, cudaEventDisableTiming);
        init_done = 1;
    }

    cudaEventRecord(eFork, 0);
    cudaStreamWaitEvent(s1, eFork, 0);
    cudaStreamWaitEvent(s2, eFork, 0);

    // ---- s1: degree + CSR ----
    k_zero_cnt<<<(NN + 255) / 256, 256, 0, s1>>>();
    k_count<<<(NE + 255) / 256, 256, 0, s1>>>(ei);
    k_scan1<<<NBLK, 1024, 0, s1>>>();
    k_scan2<<<1, 64, 0, s1>>>();
    k_scan3<<<(NN + 255) / 256, 256, 0, s1>>>();
    k_scatter<<<(NE + 255) / 256, 256, 0, s1>>>(ei);
    cudaEventRecord(eCsr, s1);

    // ---- s2: GCN weight splits ----
    k_split_t<<<(128 * 256 + 255) / 256, 256, 0, s2>>>(g1w, g1h, g1l, 128, 256);
    k_split_t<<<(256 * 512 + 255) / 256, 256, 0, s2>>>(g2w, g2h, g2l, 256, 512);
    k_split_t<<<(512 * 50 + 255) / 256, 256, 0, s2>>>(g3w, g3h, g3l, 512, 50);
    cudaEventRecord(eWts, s2);

    // ---- default: MLP weight splits + MLP chain ----
    k_split_t<<<(32 * 64 + 255) / 256, 256>>>(w2, w2h, w2l, 32, 64);
    k_split_t<<<(64 * 128 + 255) / 256, 256>>>(w3, w3h, w3l, 64, 128);

    const int MB = (NN + 127) / 128;   // 391

    k_mlp1<<<(NN + 255) / 256, 256>>>(x, w1, b1, h32h, h32l);
    k_gemm_bf<64, true, true, true><<<dim3(MB, 1), 256, dyn64>>>(
        h32h, h32l, w2h, w2l, b2, nullptr, h64h, h64l, NN, 32, 64, 64);
    k_gemm_bf<128, true, true, false><<<dim3(MB, 1), 256, dyn128>>>(
        h64h, h64l, w3h, w3l, b3, h128, nullptr, nullptr, NN, 64, 128, 128);

    cudaStreamWaitEvent(0, eCsr, 0);
    cudaStreamWaitEvent(0, eWts, 0);

    // GCN1
    k_agg4p<1><<<(NN + 7) / 8, 256>>>(h128, p128h, p128l);
    k_gemm_bf<128, true, true, false><<<dim3(MB, 2), 256, dyn128>>>(
        p128h, p128l, g1h, g1l, g1b, h256, nullptr, nullptr, NN, 128, 256, 256);

    // GCN2
    k_agg4p<2><<<(NN + 7) / 8, 256>>>(h256, p256h, p256l);
    k_gemm_bf<128, true, true, true><<<dim3(MB, 4), 256, dyn128>>>(
        p256h, p256l, g2h, g2l, g2b, nullptr, h512h, h512l, NN, 256, 512, 512);

    // GCN3: 512->50 (pad 64), then fused propagate+softmax
    k_gemm_bf<64, false, false, false><<<dim3(MB, 1), 256, dyn64>>>(
        h512h, h512l, g3h, g3l, nullptr, t64, nullptr, nullptr, NN, 512, 50, 64);
    k_agg_soft<<<(NN + 7) / 8, 256>>>(t64, g3b, out);
}

// round 16
// speedup vs baseline: 1.0522x; 1.0108x over previous
#include <cuda_runtime.h>
#include <cuda_bf16.h>
#include <cuda_fp16.h>
#include <math.h>
#include <stdint.h>

#define NN 50000
#define NE 800000
#define NBLK ((NN + 1023) / 1024)

// ---------------- scratch (static device globals; no allocation) -------------
__device__ int   g_cnt[NN];
__device__ int   g_rowptr[NN + 1];
__device__ int   g_cursor[NN];
__device__ int   g_colsrc[NE];
__device__ int   g_bsum[64];
__device__ float g_dinv[NN];

__device__ float g_h128[(size_t)NN * 128];
__device__ float g_t64 [(size_t)NN * 64];
__device__ __align__(256) __half g_h256f[(size_t)NN * 256];   // fp16 GCN2 agg input

__device__ __align__(256) __nv_bfloat16 g_h32h [(size_t)NN * 32],  g_h32l [(size_t)NN * 32];
__device__ __align__(256) __nv_bfloat16 g_h64h [(size_t)NN * 64],  g_h64l [(size_t)NN * 64];
__device__ __align__(256) __nv_bfloat16 g_p128h[(size_t)NN * 128], g_p128l[(size_t)NN * 128];
__device__ __align__(256) __nv_bfloat16 g_p256h[(size_t)NN * 256], g_p256l[(size_t)NN * 256];
__device__ __align__(256) __nv_bfloat16 g_h512h[(size_t)NN * 512], g_h512l[(size_t)NN * 512];

__device__ __align__(256) __nv_bfloat16 g_w2h[64 * 32],   g_w2l[64 * 32];
__device__ __align__(256) __nv_bfloat16 g_w3h[128 * 64],  g_w3l[128 * 64];
__device__ __align__(256) __nv_bfloat16 g_g1h[256 * 128], g_g1l[256 * 128];
__device__ __align__(256) __nv_bfloat16 g_g2h[512 * 256], g_g2l[512 * 256];
__device__ __align__(256) __nv_bfloat16 g_g3h[50 * 512],  g_g3l[50 * 512];

// ---------------- helpers ------------------------------------------------------
__device__ __forceinline__ void split1(float x, float& hi, float& lo) {
    __nv_bfloat16 h = __float2bfloat16(x);
    hi = __bfloat162float(h);
    lo = x - hi;
}
__device__ __forceinline__ void mma16(float c[4], const uint32_t a[4], uint32_t b0, uint32_t b1) {
    asm("mma.sync.aligned.m16n8k16.row.col.f32.bf16.bf16.f32 "
        "{%0,%1,%2,%3},{%4,%5,%6,%7},{%8,%9},{%0,%1,%2,%3};"
        : "+f"(c[0]), "+f"(c[1]), "+f"(c[2]), "+f"(c[3])
        : "r"(a[0]), "r"(a[1]), "r"(a[2]), "r"(a[3]), "r"(b0), "r"(b1));
}
__device__ __forceinline__ void ldm_x4(uint32_t r[4], uint32_t saddr) {
    asm volatile("ldmatrix.sync.aligned.m8n8.x4.shared.b16 {%0,%1,%2,%3}, [%4];"
        : "=r"(r[0]), "=r"(r[1]), "=r"(r[2]), "=r"(r[3]) : "r"(saddr));
}
__device__ __forceinline__ uint32_t smem_u32(const void* p) {
    uint32_t a;
    asm("{ .reg .u64 t; cvta.to.shared.u64 t, %1; cvt.u32.u64 %0, t; }" : "=r"(a) : "l"(p));
    return a;
}
__device__ __forceinline__ void cpa16(uint32_t dst, const void* src, bool pred) {
    int sz = pred ? 16 : 0;
    asm volatile("cp.async.cg.shared.global [%0], [%1], 16, %2;"
        :: "r"(dst), "l"(src), "r"(sz));
}
#define CP_COMMIT() asm volatile("cp.async.commit_group;")
#define CP_WAIT0()  asm volatile("cp.async.wait_group 0;")

// ---------------- degree / CSR build -----------------------------------------
__global__ void k_zero_cnt() {
    int i = blockIdx.x * blockDim.x + threadIdx.x;
    if (i < NN) g_cnt[i] = 0;
}
__global__ void k_count(const int* __restrict__ ei) {
    int e = blockIdx.x * blockDim.x + threadIdx.x;
    if (e < NE) {
        int dst = ei[NE + e];
        if ((unsigned)dst < NN) atomicAdd(&g_cnt[dst], 1);
    }
}
__global__ void k_scan1() {
    __shared__ int sh[1024];
    int tid = threadIdx.x;
    int i = blockIdx.x * 1024 + tid;
    int v = (i < NN) ? g_cnt[i] : 0;
    if (i < NN) g_dinv[i] = rsqrtf((float)v + 1.0f);
    sh[tid] = v;
    __syncthreads();
    for (int off = 1; off < 1024; off <<= 1) {
        int t = (tid >= off) ? sh[tid - off] : 0;
        __syncthreads();
        sh[tid] += t;
        __syncthreads();
    }
    if (i < NN) g_rowptr[i] = sh[tid] - v;
    if (tid == 1023) g_bsum[blockIdx.x] = sh[1023];
}
__global__ void k_scan2() {
    __shared__ int sh[64];
    int tid = threadIdx.x;
    int v = (tid < NBLK) ? g_bsum[tid] : 0;
    sh[tid] = v;
    __syncthreads();
    for (int off = 1; off < 64; off <<= 1) {
        int t = (tid >= off) ? sh[tid - off] : 0;
        __syncthreads();
        sh[tid] += t;
        __syncthreads();
    }
    g_bsum[tid] = sh[tid] - v;
}
__global__ void k_scan3() {
    int i = blockIdx.x * blockDim.x + threadIdx.x;
    if (i < NN) {
        int r = g_rowptr[i] + g_bsum[i >> 10];
        g_rowptr[i] = r;
        g_cursor[i] = r;
    }
    if (i == 0) g_rowptr[NN] = NE;
}
__global__ void k_scatter(const int* __restrict__ ei) {
    int e = blockIdx.x * blockDim.x + threadIdx.x;
    if (e < NE) {
        int dst = ei[NE + e];
        int src = ei[e];
        if ((unsigned)dst < NN && (unsigned)src < NN) {
            int pos = atomicAdd(&g_cursor[dst], 1);
            if ((unsigned)pos < NE) g_colsrc[pos] = src;
        }
    }
}

// ---------------- weight split + transpose -------------------------------------
__global__ void k_split_t(const float* __restrict__ src, __nv_bfloat16* __restrict__ hi,
                          __nv_bfloat16* __restrict__ lo, int K, int N) {
    int i = blockIdx.x * blockDim.x + threadIdx.x;
    if (i < K * N) {
        int k = i / N, n = i % N;
        float x = src[i];
        float h, l;
        split1(x, h, l);
        hi[(size_t)n * K + k] = __float2bfloat16(h);
        lo[(size_t)n * K + k] = __float2bfloat16(l);
    }
}

// ---------------- MLP layer 1 (K=3 -> 32), writes planes ----------------------
__global__ __launch_bounds__(256)
void k_mlp1(const float* __restrict__ x, const float* __restrict__ w,
            const float* __restrict__ b,
            __nv_bfloat16* __restrict__ hh, __nv_bfloat16* __restrict__ hl) {
    __shared__ float sw[96], sb[32];
    int tid = threadIdx.x;
    if (tid < 96) sw[tid] = w[tid];
    if (tid < 32) sb[tid] = b[tid];
    __syncthreads();
    int v = blockIdx.x * 256 + tid;
    if (v >= NN) return;
    float x0 = x[3 * v], x1 = x[3 * v + 1], x2 = x[3 * v + 2];
    __nv_bfloat162* ph = (__nv_bfloat162*)(hh + (size_t)v * 32);
    __nv_bfloat162* pl = (__nv_bfloat162*)(hl + (size_t)v * 32);
#pragma unroll
    for (int j = 0; j < 32; j += 2) {
        float h0 = fmaxf(x0 * sw[j] + x1 * sw[32 + j] + x2 * sw[64 + j] + sb[j], 0.f);
        float h1 = fmaxf(x0 * sw[j + 1] + x1 * sw[32 + j + 1] + x2 * sw[64 + j + 1] + sb[j + 1], 0.f);
        float a0, l0, a1, l1;
        split1(h0, a0, l0);
        split1(h1, a1, l1);
        ph[j >> 1] = __floats2bfloat162_rn(a0, a1);
        pl[j >> 1] = __floats2bfloat162_rn(l0, l1);
    }
}

// ---------------- bf16x3 tensor-core GEMM (cp.async staging) -------------------
// OMODE: 0 = fp32 Cf, 1 = bf16 hi/lo planes, 2 = fp16 (Cf reinterpreted as __half*)
template <int BN, bool RELU, bool BIAS, int OMODE>
__global__ __launch_bounds__(256)
void k_gemm_bf(const __nv_bfloat16* __restrict__ Ahi, const __nv_bfloat16* __restrict__ Alo,
               const __nv_bfloat16* __restrict__ Whi, const __nv_bfloat16* __restrict__ Wlo,
               const float* __restrict__ bias,
               float* __restrict__ Cf,
               __nv_bfloat16* __restrict__ Chi, __nv_bfloat16* __restrict__ Clo,
               int M, int K, int Ntrue, int Npad) {
    constexpr int BM = 128, BK = 32, ASTR = 40;
    constexpr int A_H = BM * ASTR;
    constexpr int B_H = BN * ASTR;
    constexpr int STAGE = 2 * A_H + 2 * B_H;
    constexpr int OAH = 0, OAL = A_H, OBH = 2 * A_H, OBL = 2 * A_H + B_H;
    constexpr int NJ = (BN / 2) / 8;
    constexpr int TPN = 256 / BN;
    constexpr int KSEG = BK / TPN;
    constexpr int NV = KSEG / 8;

    extern __shared__ __nv_bfloat16 sm[];
    const uint32_t smb = smem_u32(sm);
    int tid = threadIdx.x, lane = tid & 31, wid = tid >> 5;
    int wm = (wid & 3) * 32, wn = (wid >> 2) * (BN / 2);
    int bm0 = blockIdx.x * BM, bn0 = blockIdx.y * BN;

    float c[2][NJ][4];
#pragma unroll
    for (int mi = 0; mi < 2; mi++)
#pragma unroll
        for (int nj = 0; nj < NJ; nj++)
#pragma unroll
            for (int r = 0; r < 4; r++) c[mi][nj][r] = 0.f;

    int arow = tid >> 1, ahalf = tid & 1;
    int brow = tid / TPN, bseg = tid % TPN;
    bool aok = (bm0 + arow) < M;
    bool bok = (bn0 + brow) < Ntrue;
    const __nv_bfloat16* pAh = Ahi + (size_t)(bm0 + arow) * K + ahalf * 16;
    const __nv_bfloat16* pAl = Alo + (size_t)(bm0 + arow) * K + ahalf * 16;
    const __nv_bfloat16* pBh = Whi + (size_t)(bn0 + brow) * K + bseg * KSEG;
    const __nv_bfloat16* pBl = Wlo + (size_t)(bn0 + brow) * K + bseg * KSEG;
    uint32_t dA = smb + ((uint32_t)arow * ASTR + ahalf * 16) * 2;
    uint32_t dB = smb + ((uint32_t)brow * ASTR + bseg * KSEG) * 2;

    auto stage_in = [&](int kt) {
        int k0 = kt * BK;
        uint32_t so = (uint32_t)((kt & 1) * STAGE) * 2;
        cpa16(so + dA + OAH * 2,      pAh + k0,     aok);
        cpa16(so + dA + OAH * 2 + 16, pAh + k0 + 8, aok);
        cpa16(so + dA + OAL * 2,      pAl + k0,     aok);
        cpa16(so + dA + OAL * 2 + 16, pAl + k0 + 8, aok);
#pragma unroll
        for (int v = 0; v < NV; v++) {
            cpa16(so + dB + OBH * 2 + v * 16, pBh + k0 + v * 8, bok);
            cpa16(so + dB + OBL * 2 + v * 16, pBl + k0 + v * 8, bok);
        }
        CP_COMMIT();
    };

    auto comp = [&](int buf) {
        uint32_t st = smb + (uint32_t)(buf * STAGE) * 2;
#pragma unroll
        for (int ch = 0; ch < 2; ch++) {
            uint32_t ah[2][4], al[2][4];
#pragma unroll
            for (int mi = 0; mi < 2; mi++) {
                uint32_t ar = (uint32_t)(wm + mi * 16 + (lane & 15));
                uint32_t ac = (uint32_t)(ch * 16 + ((lane >> 4) << 3));
                uint32_t aoff = (ar * ASTR + ac) * 2;
                ldm_x4(ah[mi], st + OAH * 2 + aoff);
                ldm_x4(al[mi], st + OAL * 2 + aoff);
            }
            uint32_t br = (uint32_t)(wn + (lane & 7) + ((lane & 16) >> 1));
            uint32_t bc = (uint32_t)(ch * 16 + (lane & 8));
#pragma unroll
            for (int njp = 0; njp < NJ / 2; njp++) {
                uint32_t boff = ((br + njp * 16) * ASTR + bc) * 2;
                uint32_t bh[4], bl[4];
                ldm_x4(bh, st + OBH * 2 + boff);
                ldm_x4(bl, st + OBL * 2 + boff);
#pragma unroll
                for (int mi = 0; mi < 2; mi++) {
                    mma16(c[mi][2 * njp], al[mi], bh[0], bh[1]);
                    mma16(c[mi][2 * njp], ah[mi], bl[0], bl[1]);
                    mma16(c[mi][2 * njp], ah[mi], bh[0], bh[1]);
                    mma16(c[mi][2 * njp + 1], al[mi], bh[2], bh[3]);
                    mma16(c[mi][2 * njp + 1], ah[mi], bl[2], bl[3]);
                    mma16(c[mi][2 * njp + 1], ah[mi], bh[2], bh[3]);
                }
            }
        }
    };

    const int T = K / BK;
    stage_in(0);
    for (int kt = 0; kt < T; kt++) {
        CP_WAIT0();
        __syncthreads();
        if (kt + 1 < T) stage_in(kt + 1);
        comp(kt & 1);
        __syncthreads();
    }

    // epilogue
#pragma unroll
    for (int mi = 0; mi < 2; mi++) {
#pragma unroll
        for (int nj = 0; nj < NJ; nj++) {
            int row0 = bm0 + wm + mi * 16 + (lane >> 2);
            int col = bn0 + wn + nj * 8 + (lane & 3) * 2;
            float v0 = c[mi][nj][0], v1 = c[mi][nj][1];
            float v2 = c[mi][nj][2], v3 = c[mi][nj][3];
            if (BIAS) {
                float bb0 = (col < Ntrue) ? bias[col] : 0.f;
                float bb1 = (col + 1 < Ntrue) ? bias[col + 1] : 0.f;
                v0 += bb0; v1 += bb1; v2 += bb0; v3 += bb1;
            }
            if (RELU) {
                v0 = fmaxf(v0, 0.f); v1 = fmaxf(v1, 0.f);
                v2 = fmaxf(v2, 0.f); v3 = fmaxf(v3, 0.f);
            }
            if (OMODE == 1) {
                float h0, l0, h1, l1;
                if (row0 < M) {
                    split1(v0, h0, l0); split1(v1, h1, l1);
                    *(__nv_bfloat162*)(Chi + (size_t)row0 * Npad + col) = __floats2bfloat162_rn(h0, h1);
                    *(__nv_bfloat162*)(Clo + (size_t)row0 * Npad + col) = __floats2bfloat162_rn(l0, l1);
                }
                if (row0 + 8 < M) {
                    split1(v2, h0, l0); split1(v3, h1, l1);
                    *(__nv_bfloat162*)(Chi + (size_t)(row0 + 8) * Npad + col) = __floats2bfloat162_rn(h0, h1);
                    *(__nv_bfloat162*)(Clo + (size_t)(row0 + 8) * Npad + col) = __floats2bfloat162_rn(l0, l1);
                }
            } else if (OMODE == 2) {
                __half* Ch16 = (__half*)Cf;
                if (row0 < M)
                    *(__half2*)(Ch16 + (size_t)row0 * Npad + col) = __floats2half2_rn(v0, v1);
                if (row0 + 8 < M)
                    *(__half2*)(Ch16 + (size_t)(row0 + 8) * Npad + col) = __floats2half2_rn(v2, v3);
            } else {
                if (row0 < M)
                    *(float2*)&Cf[(size_t)row0 * Npad + col] = make_float2(v0, v1);
                if (row0 + 8 < M)
                    *(float2*)&Cf[(size_t)(row0 + 8) * Npad + col] = make_float2(v2, v3);
            }
        }
    }
}

// ---------------- GCN propagation: fp32 in, bf16 planes out (F=128) -----------
template <int C4>
__global__ void k_agg4p(const float* __restrict__ h,
                        __nv_bfloat16* __restrict__ phi, __nv_bfloat16* __restrict__ plo) {
    int v = blockIdx.x * 8 + (threadIdx.x >> 5);
    if (v >= NN) return;
    int lane = threadIdx.x & 31;
    constexpr int F = C4 * 128;
    float dv = g_dinv[v];
    const float4* hv = (const float4*)(h + (size_t)v * F);
    float4 acc[C4];
    float s2 = dv * dv;
#pragma unroll
    for (int i = 0; i < C4; i++) {
        float4 t = hv[lane + i * 32];
        acc[i] = make_float4(t.x * s2, t.y * s2, t.z * s2, t.w * s2);
    }
    int e = g_rowptr[v], end = g_rowptr[v + 1];
    for (; e < end; e++) {
        int s = g_colsrc[e];
        if ((unsigned)s >= NN) continue;
        float nrm = dv * g_dinv[s];
        const float4* hs = (const float4*)(h + (size_t)s * F);
#pragma unroll
        for (int i = 0; i < C4; i++) {
            float4 t = hs[lane + i * 32];
            acc[i].x += nrm * t.x; acc[i].y += nrm * t.y;
            acc[i].z += nrm * t.z; acc[i].w += nrm * t.w;
        }
    }
#pragma unroll
    for (int i = 0; i < C4; i++) {
        int base = 4 * (lane + i * 32);
        float hx, lx, hy, ly, hz, lz, hw, lw;
        split1(acc[i].x, hx, lx); split1(acc[i].y, hy, ly);
        split1(acc[i].z, hz, lz); split1(acc[i].w, hw, lw);
        *(__nv_bfloat162*)(phi + (size_t)v * F + base)     = __floats2bfloat162_rn(hx, hy);
        *(__nv_bfloat162*)(phi + (size_t)v * F + base + 2) = __floats2bfloat162_rn(hz, hw);
        *(__nv_bfloat162*)(plo + (size_t)v * F + base)     = __floats2bfloat162_rn(lx, ly);
        *(__nv_bfloat162*)(plo + (size_t)v * F + base + 2) = __floats2bfloat162_rn(lz, lw);
    }
}

// ---------------- GCN2 propagation: fp16 in (half traffic), bf16 planes out ----
__global__ void k_agg4p_h(const __half* __restrict__ h,
                          __nv_bfloat16* __restrict__ phi, __nv_bfloat16* __restrict__ plo) {
    int v = blockIdx.x * 8 + (threadIdx.x >> 5);
    if (v >= NN) return;
    int lane = threadIdx.x & 31;
    float dv = g_dinv[v];
    float s2 = dv * dv;
    float acc[8];
    {
        uint4 raw = *(const uint4*)(h + (size_t)v * 256 + lane * 8);
        const __half2* p = (const __half2*)&raw;
#pragma unroll
        for (int i = 0; i < 4; i++) {
            float2 f = __half22float2(p[i]);
            acc[2 * i] = f.x * s2;
            acc[2 * i + 1] = f.y * s2;
        }
    }
    int e = g_rowptr[v], end = g_rowptr[v + 1];
    for (; e < end; e++) {
        int s = g_colsrc[e];
        if ((unsigned)s >= NN) continue;
        float nrm = dv * g_dinv[s];
        uint4 raw = *(const uint4*)(h + (size_t)s * 256 + lane * 8);
        const __half2* p = (const __half2*)&raw;
#pragma unroll
        for (int i = 0; i < 4; i++) {
            float2 f = __half22float2(p[i]);
            acc[2 * i] += nrm * f.x;
            acc[2 * i + 1] += nrm * f.y;
        }
    }
    size_t base = (size_t)v * 256 + lane * 8;
#pragma unroll
    for (int i = 0; i < 8; i += 2) {
        float h0, l0, h1, l1;
        split1(acc[i], h0, l0);
        split1(acc[i + 1], h1, l1);
        *(__nv_bfloat162*)(phi + base + i) = __floats2bfloat162_rn(h0, h1);
        *(__nv_bfloat162*)(plo + base + i) = __floats2bfloat162_rn(l0, l1);
    }
}

// ---------------- fused final aggregation + bias + softmax ---------------------
__global__ void k_agg_soft(const float* __restrict__ h, const float* __restrict__ b,
                           float* __restrict__ out) {
    int v = blockIdx.x * 8 + (threadIdx.x >> 5);
    if (v >= NN) return;
    int lane = threadIdx.x & 31;
    float dv = g_dinv[v];
    float2 a = ((const float2*)(h + (size_t)v * 64))[lane];
    float s2 = dv * dv;
    a.x *= s2; a.y *= s2;
    int e = g_rowptr[v], end = g_rowptr[v + 1];
    for (; e < end; e++) {
        int s = g_colsrc[e];
        if ((unsigned)s >= NN) continue;
        float nrm = dv * g_dinv[s];
        float2 t = ((const float2*)(h + (size_t)s * 64))[lane];
        a.x += nrm * t.x; a.y += nrm * t.y;
    }
    int c0 = 2 * lane, c1 = 2 * lane + 1;
    float v0 = (c0 < 50) ? (a.x + b[c0]) : -1e30f;
    float v1 = (c1 < 50) ? (a.y + b[c1]) : -1e30f;
    float m = fmaxf(v0, v1);
#pragma unroll
    for (int off = 16; off >= 1; off >>= 1)
        m = fmaxf(m, __shfl_xor_sync(0xffffffffu, m, off));
    float e0 = (c0 < 50) ? __expf(v0 - m) : 0.f;
    float e1 = (c1 < 50) ? __expf(v1 - m) : 0.f;
    float s = e0 + e1;
#pragma unroll
    for (int off = 16; off >= 1; off >>= 1)
        s += __shfl_xor_sync(0xffffffffu, s, off);
    float inv = 1.0f / s;
    if (c0 < 50) out[(size_t)v * 50 + c0] = e0 * inv;
    if (c1 < 50) out[(size_t)v * 50 + c1] = e1 * inv;
}

// ---------------- launch ------------------------------------------------------
static inline void* sym(const void* s) {
    void* p = nullptr;
    cudaGetSymbolAddress(&p, s);
    return p;
}

extern "C" void kernel_launch(void* const* d_in, const int* in_sizes, int n_in,
                              void* d_out, int out_size) {
    const float* x   = (const float*)d_in[0];
    const int*   ei  = (const int*)d_in[1];
    const float* w1  = (const float*)d_in[2];
    const float* b1  = (const float*)d_in[3];
    const float* w2  = (const float*)d_in[4];
    const float* b2  = (const float*)d_in[5];
    const float* w3  = (const float*)d_in[6];
    const float* b3  = (const float*)d_in[7];
    const float* g1w = (const float*)d_in[8];
    const float* g1b = (const float*)d_in[9];
    const float* g2w = (const float*)d_in[10];
    const float* g2b = (const float*)d_in[11];
    const float* g3w = (const float*)d_in[12];
    const float* g3b = (const float*)d_in[13];
    float* out = (float*)d_out;

    float* h128 = (float*)sym(g_h128);
    float* t64  = (float*)sym(g_t64);
    __half* h256f = (__half*)sym(g_h256f);

    __nv_bfloat16* h32h = (__nv_bfloat16*)sym(g_h32h);
    __nv_bfloat16* h32l = (__nv_bfloat16*)sym(g_h32l);
    __nv_bfloat16* h64h = (__nv_bfloat16*)sym(g_h64h);
    __nv_bfloat16* h64l = (__nv_bfloat16*)sym(g_h64l);
    __nv_bfloat16* p128h = (__nv_bfloat16*)sym(g_p128h);
    __nv_bfloat16* p128l = (__nv_bfloat16*)sym(g_p128l);
    __nv_bfloat16* p256h = (__nv_bfloat16*)sym(g_p256h);
    __nv_bfloat16* p256l = (__nv_bfloat16*)sym(g_p256l);
    __nv_bfloat16* h512h = (__nv_bfloat16*)sym(g_h512h);
    __nv_bfloat16* h512l = (__nv_bfloat16*)sym(g_h512l);

    __nv_bfloat16* w2h = (__nv_bfloat16*)sym(g_w2h);
    __nv_bfloat16* w2l = (__nv_bfloat16*)sym(g_w2l);
    __nv_bfloat16* w3h = (__nv_bfloat16*)sym(g_w3h);
    __nv_bfloat16* w3l = (__nv_bfloat16*)sym(g_w3l);
    __nv_bfloat16* g1h = (__nv_bfloat16*)sym(g_g1h);
    __nv_bfloat16* g1l = (__nv_bfloat16*)sym(g_g1l);
    __nv_bfloat16* g2h = (__nv_bfloat16*)sym(g_g2h);
    __nv_bfloat16* g2l = (__nv_bfloat16*)sym(g_g2l);
    __nv_bfloat16* g3h = (__nv_bfloat16*)sym(g_g3h);
    __nv_bfloat16* g3l = (__nv_bfloat16*)sym(g_g3l);

    const int dyn128 = (2 * 128 * 40 + 2 * 128 * 40) * 2 * 2;  // 81920
    const int dyn64  = (2 * 128 * 40 + 2 * 64 * 40) * 2 * 2;   // 61440

    static cudaStream_t s1 = nullptr, s2 = nullptr;
    static cudaEvent_t eFork = nullptr, eCsr = nullptr, eWts = nullptr;
    static int init_done = 0;
    if (!init_done) {
        cudaFuncSetAttribute(k_gemm_bf<64, true, true, 1>,
                             cudaFuncAttributeMaxDynamicSharedMemorySize, dyn64);
        cudaFuncSetAttribute(k_gemm_bf<128, true, true, 0>,
                             cudaFuncAttributeMaxDynamicSharedMemorySize, dyn128);
        cudaFuncSetAttribute(k_gemm_bf<128, true, true, 2>,
                             cudaFuncAttributeMaxDynamicSharedMemorySize, dyn128);
        cudaFuncSetAttribute(k_gemm_bf<128, true, true, 1>,
                             cudaFuncAttributeMaxDynamicSharedMemorySize, dyn128);
        cudaFuncSetAttribute(k_gemm_bf<64, false, false, 0>,
                             cudaFuncAttributeMaxDynamicSharedMemorySize, dyn64);
        cudaStreamCreateWithFlags(&s1, cudaStreamNonBlocking);
        cudaStreamCreateWithFlags(&s2, cudaStreamNonBlocking);
        cudaEventCreateWithFlags(&eFork, cudaEventDisableTiming);
        cudaEventCreateWithFlags(&eCsr, cudaEventDisableTiming);
        cudaEventCreateWithFlags(&eWts, cudaEventDisableTiming);
        init_done = 1;
    }

    cudaEventRecord(eFork, 0);
    cudaStreamWaitEvent(s1, eFork, 0);
    cudaStreamWaitEvent(s2, eFork, 0);

    // ---- s1: degree + CSR ----
    k_zero_cnt<<<(NN + 255) / 256, 256, 0, s1>>>();
    k_count<<<(NE + 255) / 256, 256, 0, s1>>>(ei);
    k_scan1<<<NBLK, 1024, 0, s1>>>();
    k_scan2<<<1, 64, 0, s1>>>();
    k_scan3<<<(NN + 255) / 256, 256, 0, s1>>>();
    k_scatter<<<(NE + 255) / 256, 256, 0, s1>>>(ei);
    cudaEventRecord(eCsr, s1);

    // ---- s2: GCN weight splits ----
    k_split_t<<<(128 * 256 + 255) / 256, 256, 0, s2>>>(g1w, g1h, g1l, 128, 256);
    k_split_t<<<(256 * 512 + 255) / 256, 256, 0, s2>>>(g2w, g2h, g2l, 256, 512);
    k_split_t<<<(512 * 50 + 255) / 256, 256, 0, s2>>>(g3w, g3h, g3l, 512, 50);
    cudaEventRecord(eWts, s2);

    // ---- default: MLP weight splits + MLP chain ----
    k_split_t<<<(32 * 64 + 255) / 256, 256>>>(w2, w2h, w2l, 32, 64);
    k_split_t<<<(64 * 128 + 255) / 256, 256>>>(w3, w3h, w3l, 64, 128);

    const int MB = (NN + 127) / 128;   // 391

    k_mlp1<<<(NN + 255) / 256, 256>>>(x, w1, b1, h32h, h32l);
    k_gemm_bf<64, true, true, 1><<<dim3(MB, 1), 256, dyn64>>>(
        h32h, h32l, w2h, w2l, b2, nullptr, h64h, h64l, NN, 32, 64, 64);
    k_gemm_bf<128, true, true, 0><<<dim3(MB, 1), 256, dyn128>>>(
        h64h, h64l, w3h, w3l, b3, h128, nullptr, nullptr, NN, 64, 128, 128);

    cudaStreamWaitEvent(0, eCsr, 0);
    cudaStreamWaitEvent(0, eWts, 0);

    // GCN1: agg fp32, GEMM outputs fp16 (feeds GCN2 agg)
    k_agg4p<1><<<(NN + 7) / 8, 256>>>(h128, p128h, p128l);
    k_gemm_bf<128, true, true, 2><<<dim3(MB, 2), 256, dyn128>>>(
        p128h, p128l, g1h, g1l, g1b, (float*)h256f, nullptr, nullptr, NN, 128, 256, 256);

    // GCN2: fp16 agg (half gather traffic), GEMM planes out
    k_agg4p_h<<<(NN + 7) / 8, 256>>>(h256f, p256h, p256l);
    k_gemm_bf<128, true, true, 1><<<dim3(MB, 4), 256, dyn128>>>(
        p256h, p256l, g2h, g2l, g2b, nullptr, h512h, h512l, NN, 256, 512, 512);

    // GCN3: 512->50 (pad 64), then fused propagate+softmax
    k_gemm_bf<64, false, false, 0><<<dim3(MB, 1), 256, dyn64>>>(
        h512h, h512l, g3h, g3l, nullptr, t64, nullptr, nullptr, NN, 512, 50, 64);
    k_agg_soft<<<(NN + 7) / 8, 256>>>(t64, g3b, out);
}